// round 12
// baseline (speedup 1.0000x reference)
#include <cuda_runtime.h>
#include <stdint.h>
#include <math.h>

#define BB 4
#define TT 2048
#define CC 768
#define HH 12
#define HS 64
#define C3 (3*CC)

// ---------------- scratch (static device globals; no allocations) ----------------
__device__ float g_qkv[(size_t)BB*TT*C3];   // (B,T,3C) tf32 bits
__device__ float g_atty[(size_t)BB*TT*CC];  // (B,T,C) tf32 bits
__device__ float g_imp[BB*TT];              // unnormalized importance accumulator
__device__ float g_xb[(size_t)BB*TT*CC];    // x as tf32 bits
__device__ float g_wab[(size_t)CC*C3];      // w_attn as tf32 bits
__device__ float g_wpb[(size_t)CC*CC];      // w_proj as tf32 bits

// ---------------- helpers ----------------------------------------------------------
__device__ __forceinline__ unsigned int f2tf32(float x) {
    unsigned int r;
    asm("cvt.rna.tf32.f32 %0, %1;" : "=r"(r) : "f"(x));
    return r;
}

__device__ __forceinline__ float ex2f(float x) {
    float r;
    asm("ex2.approx.f32 %0, %1;" : "=f"(r) : "f"(x));
    return r;
}

__device__ __forceinline__ void mma_tf32(float c[4], const unsigned int a[4], const unsigned int b[2]) {
    asm volatile(
        "mma.sync.aligned.m16n8k8.row.col.f32.tf32.tf32.f32 "
        "{%0,%1,%2,%3}, {%4,%5,%6,%7}, {%8,%9}, {%0,%1,%2,%3};"
        : "+f"(c[0]), "+f"(c[1]), "+f"(c[2]), "+f"(c[3])
        : "r"(a[0]), "r"(a[1]), "r"(a[2]), "r"(a[3]), "r"(b[0]), "r"(b[1]));
}

__device__ __forceinline__ void cp16(void* smem_ptr, const void* gptr) {
    unsigned int sa = (unsigned int)__cvta_generic_to_shared(smem_ptr);
    asm volatile("cp.async.cg.shared.global [%0], [%1], 16;\n" :: "r"(sa), "l"(gptr));
}
#define CP_COMMIT() asm volatile("cp.async.commit_group;\n")
#define CP_WAIT1()  asm volatile("cp.async.wait_group 1;\n")
#define CP_WAIT0()  asm volatile("cp.async.wait_group 0;\n")

#define C1SC 0.18033688f   // 0.125 * log2(e): softmax scale folded into ex2 argument

// ---------------- fp32 -> tf32-bits elementwise ------------------------------------
__global__ void cvt_tf32_kernel(const float4* __restrict__ src, float4* __restrict__ dst, int n4) {
    int i = blockIdx.x*256 + threadIdx.x;
    if (i < n4) {
        float4 v = src[i];
        v.x = __uint_as_float(f2tf32(v.x));
        v.y = __uint_as_float(f2tf32(v.y));
        v.z = __uint_as_float(f2tf32(v.z));
        v.w = __uint_as_float(f2tf32(v.w));
        dst[i] = v;
    }
}

// ---------------- tf32 tensor-core GEMM (inputs pre-converted to tf32 bits) --------
// 128x128x32 tile, 256 thr, 3-stage cp.async pipeline, ONE __syncthreads per k-tile.
#define AST 36
#define BST 136
#define GSTAGE_W (128*AST + 32*BST)   // words per pipeline stage

template<bool CONVOUT>
__global__ __launch_bounds__(256, 2) void gemm_tf32(
        const unsigned int* __restrict__ A, const unsigned int* __restrict__ Bw,
        float* __restrict__ Cm, int M, int N, int K) {
    extern __shared__ unsigned int gsm[];   // [3][GSTAGE_W]

    int tid = threadIdx.x;
    int lane = tid & 31, warp = tid >> 5;
    int wm = warp >> 2;
    int wn = warp & 3;
    int g = lane >> 2, t = lane & 3;

    int m0 = blockIdx.y * 128, n0 = blockIdx.x * 128;

    int arow = tid >> 3;            // 0..31 (+32*i)
    int acol = (tid & 7) * 4;       // 0..28
    int brow = tid >> 5;            // 0..7 (+8*i)
    int bcol = (tid & 31) * 4;      // 0..124

    const unsigned int* Ag = A + (size_t)(m0 + arow)*K + acol;
    const unsigned int* Bg = Bw + (size_t)brow*N + n0 + bcol;

    float acc[4][4][4];
    #pragma unroll
    for (int i = 0; i < 4; i++)
        #pragma unroll
        for (int j = 0; j < 4; j++)
            #pragma unroll
            for (int r = 0; r < 4; r++) acc[i][j][r] = 0.f;

    int nkt = K / 32;

    auto stage = [&](int kt, int bsel) {
        unsigned int* Ad = gsm + bsel*GSTAGE_W;
        unsigned int* Bd = Ad + 128*AST;
        #pragma unroll
        for (int i = 0; i < 4; i++) {
            cp16(Ad + (arow + 32*i)*AST + acol, Ag + kt*32 + (size_t)(32*i)*K);
            cp16(Bd + (brow + 8*i)*BST + bcol, Bg + (size_t)(kt*32 + 8*i)*N);
        }
    };

    stage(0, 0); CP_COMMIT();
    stage(1, 1); CP_COMMIT();

    for (int kt = 0; kt < nkt; kt++) {
        CP_WAIT1();            // buffer kt%3 ready (two groups pending at top)
        __syncthreads();       // all warps done with buffer (kt-1)%3 reads
        if (kt + 2 < nkt) stage(kt+2, (kt+2)%3);
        CP_COMMIT();           // always commit (possibly empty) -> uniform counts

        const unsigned int* Ab = gsm + (kt%3)*GSTAGE_W;
        const unsigned int* Bb = Ab + 128*AST;

        #pragma unroll
        for (int ks = 0; ks < 4; ks++) {
            int k = ks * 8;
            unsigned int af[4][4];
            #pragma unroll
            for (int mt = 0; mt < 4; mt++) {
                int r0 = wm*64 + mt*16;
                af[mt][0] = Ab[(r0+g)*AST + k + t];
                af[mt][1] = Ab[(r0+g+8)*AST + k + t];
                af[mt][2] = Ab[(r0+g)*AST + k + t + 4];
                af[mt][3] = Ab[(r0+g+8)*AST + k + t + 4];
            }
            unsigned int bf[4][2];
            #pragma unroll
            for (int nt = 0; nt < 4; nt++) {
                int c0 = wn*32 + nt*8 + g;
                bf[nt][0] = Bb[(k+t)*BST + c0];
                bf[nt][1] = Bb[(k+t+4)*BST + c0];
            }
            #pragma unroll
            for (int mt = 0; mt < 4; mt++)
                #pragma unroll
                for (int nt = 0; nt < 4; nt++)
                    mma_tf32(acc[mt][nt], af[mt], bf[nt]);
        }
    }

    #pragma unroll
    for (int mt = 0; mt < 4; mt++) {
        int r = m0 + wm*64 + mt*16 + g;
        #pragma unroll
        for (int nt = 0; nt < 4; nt++) {
            int c = n0 + wn*32 + nt*8 + t*2;
            if (CONVOUT) {
                *(float2*)&Cm[(size_t)r*N + c] = make_float2(
                    __uint_as_float(f2tf32(acc[mt][nt][0])),
                    __uint_as_float(f2tf32(acc[mt][nt][1])));
                *(float2*)&Cm[(size_t)(r+8)*N + c] = make_float2(
                    __uint_as_float(f2tf32(acc[mt][nt][2])),
                    __uint_as_float(f2tf32(acc[mt][nt][3])));
            } else {
                *(float2*)&Cm[(size_t)r*N + c]     = make_float2(acc[mt][nt][0], acc[mt][nt][1]);
                *(float2*)&Cm[(size_t)(r+8)*N + c] = make_float2(acc[mt][nt][2], acc[mt][nt][3]);
            }
        }
    }
}

// ---------------- mma attention: grid (T/128, H, B), block 256 (8 warps) ----------
// Two-pass flash. V tile single-buffered -> smem 88.6KB -> 2 CTAs/SM (16 warps).
#define KST 68
#define VST 72

__device__ __forceinline__ void stage64(unsigned int* dst, int dstride,
                                        const unsigned int* src, int tid) {
    #pragma unroll
    for (int i = tid; i < 1024; i += 256) {
        int r = i >> 4, c = (i & 15) << 2;
        cp16(dst + r*dstride + c, src + (size_t)r*C3 + c);
    }
}

__global__ __launch_bounds__(256, 2) void attn_mma(const int* __restrict__ amask) {
    extern __shared__ unsigned int smu[];
    unsigned int* Ks = smu;                      // [2][64*KST]
    unsigned int* Vs = smu + 2*64*KST;           // [64*VST]  (single buffer)
    unsigned int* Ps = Vs + 64*VST;              // [128*KST] (Q staging, then P)
    float* kvl = (float*)(Ps + 128*KST);         // [2][64] additive key mask (0/-1e30)

    const int tid = threadIdx.x;
    const int lane = tid & 31, warp = tid >> 5;
    const int g = lane >> 2, t = lane & 3;
    const int qt = (TT/128 - 1) - blockIdx.x;    // longest blocks first
    const int h = blockIdx.y, b = blockIdx.z;
    const int qbase = qt*128;
    const int nkt = 2*qt + 2;

    const unsigned int* qkvu = (const unsigned int*)g_qkv;
    const unsigned int* qsrc = qkvu + (size_t)(b*TT+qbase)*C3 + h*HS;
    const unsigned int* kall = qkvu + (size_t)(b*TT)*C3 + CC + h*HS;
    const unsigned int* vall = qkvu + (size_t)(b*TT)*C3 + 2*CC + h*HS;

    const int wrow0 = qbase + warp*16;           // warp's lowest q row
    const int gr0 = wrow0 + g;
    const int gr1 = gr0 + 8;

    // ---- prologue: stage Q (128 rows) -> Ps and K0 -> Ks[0] ----
    #pragma unroll
    for (int i = tid; i < 2048; i += 256) {
        int r = i >> 4, c = (i & 15) << 2;
        cp16(Ps + r*KST + c, qsrc + (size_t)r*C3 + c);
    }
    stage64(Ks, KST, kall, tid);
    if (tid < 64) kvl[tid] = amask[b*TT + tid] ? 0.f : -1e30f;
    CP_COMMIT();
    CP_WAIT0();
    __syncthreads();

    unsigned int qa[8][4];
    const int qrow = warp*16 + g;
    #pragma unroll
    for (int c = 0; c < 8; c++) {
        qa[c][0] = Ps[qrow*KST + 8*c + t];
        qa[c][1] = Ps[(qrow+8)*KST + 8*c + t];
        qa[c][2] = Ps[qrow*KST + 8*c + t + 4];
        qa[c][3] = Ps[(qrow+8)*KST + 8*c + t + 4];
    }

    float l0 = 0.f, l1 = 0.f;

    // ================= Pass A: row sums (K double-buffered) =======================
    for (int kt = 0; kt < nkt; kt++) {
        const int kbase = kt*64;
        CP_WAIT0();
        __syncthreads();
        if (kt + 1 < nkt) {
            stage64(Ks + ((kt+1)&1)*64*KST, KST, kall + (size_t)(kbase+64)*C3, tid);
            if (tid < 64) kvl[((kt+1)&1)*64 + tid] = amask[b*TT + kbase+64 + tid] ? 0.f : -1e30f;
        }
        CP_COMMIT();

        const unsigned int* K0 = Ks + (kt&1)*64*KST;
        const float* kv = kvl + (kt&1)*64;

        float s[8][4];
        #pragma unroll
        for (int j = 0; j < 8; j++) { s[j][0]=s[j][1]=s[j][2]=s[j][3]=0.f; }
        #pragma unroll
        for (int c = 0; c < 8; c++) {
            #pragma unroll
            for (int j = 0; j < 8; j++) {
                unsigned int bf[2];
                bf[0] = K0[(8*j+g)*KST + 8*c + t];
                bf[1] = K0[(8*j+g)*KST + 8*c + t + 4];
                mma_tf32(s[j], qa[c], bf);
            }
        }
        float ts0 = 0.f, ts1 = 0.f;
        if (kbase + 63 <= wrow0) {   // interior: no causal masking for this warp
            #pragma unroll
            for (int j = 0; j < 8; j++) {
                float kv0 = kv[8*j+2*t], kv1 = kv[8*j+2*t+1];
                ts0 += ex2f(fmaf(s[j][0], C1SC, kv0)) + ex2f(fmaf(s[j][1], C1SC, kv1));
                ts1 += ex2f(fmaf(s[j][2], C1SC, kv0)) + ex2f(fmaf(s[j][3], C1SC, kv1));
            }
        } else {                     // diagonal: full causal check
            #pragma unroll
            for (int j = 0; j < 8; j++) {
                int c0 = kbase + 8*j + 2*t;
                float kv0 = kv[8*j+2*t], kv1 = kv[8*j+2*t+1];
                float v0 = fmaf(s[j][0], C1SC, kv0); if (c0   > gr0) v0 = -1e30f;
                float v1 = fmaf(s[j][1], C1SC, kv1); if (c0+1 > gr0) v1 = -1e30f;
                float v2 = fmaf(s[j][2], C1SC, kv0); if (c0   > gr1) v2 = -1e30f;
                float v3 = fmaf(s[j][3], C1SC, kv1); if (c0+1 > gr1) v3 = -1e30f;
                ts0 += ex2f(v0) + ex2f(v1);
                ts1 += ex2f(v2) + ex2f(v3);
            }
        }
        ts0 += __shfl_xor_sync(0xffffffffu, ts0, 1);
        ts0 += __shfl_xor_sync(0xffffffffu, ts0, 2);
        ts1 += __shfl_xor_sync(0xffffffffu, ts1, 1);
        ts1 += __shfl_xor_sync(0xffffffffu, ts1, 2);
        l0 += ts0;
        l1 += ts1;
    }
    const float li0 = 1.0f/l0, li1 = 1.0f/l1;

    // ================= Pass B: output + importance (V single-buffered) ============
    float o[8][4];
    #pragma unroll
    for (int j = 0; j < 8; j++) { o[j][0]=o[j][1]=o[j][2]=o[j][3]=0.f; }

    __syncthreads();   // all warps done reading Ks/kvl from pass A before restage
    stage64(Ks, KST, kall, tid);
    stage64(Vs, VST, vall, tid);
    if (tid < 64) kvl[tid] = amask[b*TT + tid] ? 0.f : -1e30f;
    CP_COMMIT();

    for (int kt = 0; kt < nkt; kt++) {
        const int kbase = kt*64;
        CP_WAIT0();        // K[kt] and V[kt] staged
        __syncthreads();
        if (kt + 1 < nkt) {
            stage64(Ks + ((kt+1)&1)*64*KST, KST, kall + (size_t)(kbase+64)*C3, tid);
            if (tid < 64) kvl[((kt+1)&1)*64 + tid] = amask[b*TT + kbase+64 + tid] ? 0.f : -1e30f;
        }
        CP_COMMIT();

        const unsigned int* K0 = Ks + (kt&1)*64*KST;
        const float* kv = kvl + (kt&1)*64;

        float s[8][4];
        #pragma unroll
        for (int j = 0; j < 8; j++) { s[j][0]=s[j][1]=s[j][2]=s[j][3]=0.f; }
        #pragma unroll
        for (int c = 0; c < 8; c++) {
            #pragma unroll
            for (int j = 0; j < 8; j++) {
                unsigned int bf[2];
                bf[0] = K0[(8*j+g)*KST + 8*c + t];
                bf[1] = K0[(8*j+g)*KST + 8*c + t + 4];
                mma_tf32(s[j], qa[c], bf);
            }
        }
        const bool interior = (kbase + 63 <= wrow0);
        float* imp_base = &g_imp[b*TT + kbase];
        #pragma unroll
        for (int j = 0; j < 8; j++) {
            int c0 = kbase + 8*j + 2*t;
            float kv0 = kv[8*j+2*t], kv1 = kv[8*j+2*t+1];
            float v0 = fmaf(s[j][0], C1SC, kv0);
            float v1 = fmaf(s[j][1], C1SC, kv1);
            float v2 = fmaf(s[j][2], C1SC, kv0);
            float v3 = fmaf(s[j][3], C1SC, kv1);
            if (!interior) {
                if (c0   > gr0) v0 = -1e30f;
                if (c0+1 > gr0) v1 = -1e30f;
                if (c0   > gr1) v2 = -1e30f;
                if (c0+1 > gr1) v3 = -1e30f;
            }
            float p0 = ex2f(v0) * li0;
            float p1 = ex2f(v1) * li0;
            float p2 = ex2f(v2) * li1;
            float p3 = ex2f(v3) * li1;
            *(uint2*)&Ps[(warp*16+g)*KST   + 8*j + 2*t] = make_uint2(f2tf32(p0), f2tf32(p1));
            *(uint2*)&Ps[(warp*16+g+8)*KST + 8*j + 2*t] = make_uint2(f2tf32(p2), f2tf32(p3));
            float cA = p0 + p2;
            float cB = p1 + p3;
            cA += __shfl_xor_sync(0xffffffffu, cA, 4);
            cA += __shfl_xor_sync(0xffffffffu, cA, 8);
            cA += __shfl_xor_sync(0xffffffffu, cA, 16);
            cB += __shfl_xor_sync(0xffffffffu, cB, 4);
            cB += __shfl_xor_sync(0xffffffffu, cB, 8);
            cB += __shfl_xor_sync(0xffffffffu, cB, 16);
            if (g == 0) {
                atomicAdd(imp_base + 8*j + 2*t,     cA);
                atomicAdd(imp_base + 8*j + 2*t + 1, cB);
            }
        }
        // O += P @ V  (reads only this warp's own Ps rows + shared Vs)
        #pragma unroll
        for (int c = 0; c < 8; c++) {
            unsigned int pa[4];
            pa[0] = Ps[(warp*16+g)*KST   + 8*c + t];
            pa[1] = Ps[(warp*16+g+8)*KST + 8*c + t];
            pa[2] = Ps[(warp*16+g)*KST   + 8*c + t + 4];
            pa[3] = Ps[(warp*16+g+8)*KST + 8*c + t + 4];
            #pragma unroll
            for (int j = 0; j < 8; j++) {
                unsigned int bv[2];
                bv[0] = Vs[(8*c+t)*VST   + 8*j + g];
                bv[1] = Vs[(8*c+t+4)*VST + 8*j + g];
                mma_tf32(o[j], pa, bv);
            }
        }
        // restage V[kt+1] into the single V buffer once ALL warps finished PV
        __syncthreads();
        if (kt + 1 < nkt)
            stage64(Vs, VST, vall + (size_t)(kbase+64)*C3, tid);
        CP_COMMIT();
    }

    // write O to g_atty as tf32 bits (consumed by proj GEMM)
    float* ydst = g_atty + (size_t)(b*TT)*CC + h*HS;
    #pragma unroll
    for (int j = 0; j < 8; j++) {
        int col = 8*j + 2*t;
        *(float2*)&ydst[(size_t)gr0*CC + col] = make_float2(
            __uint_as_float(f2tf32(o[j][0])), __uint_as_float(f2tf32(o[j][1])));
        *(float2*)&ydst[(size_t)gr1*CC + col] = make_float2(
            __uint_as_float(f2tf32(o[j][2])), __uint_as_float(f2tf32(o[j][3])));
    }
}

__global__ void zero_imp_kernel() {
    int i = blockIdx.x*256 + threadIdx.x;
    if (i < BB*TT) g_imp[i] = 0.f;
}

__global__ void finalize_imp_kernel(float* __restrict__ out) {
    int i = blockIdx.x*256 + threadIdx.x;
    if (i < BB*TT) out[i] = g_imp[i] * (1.0f / (HH * (float)TT));
}

extern "C" void kernel_launch(void* const* d_in, const int* in_sizes, int n_in,
                              void* d_out, int out_size) {
    const float* x      = (const float*)d_in[0];
    const int*   amask  = (const int*)d_in[1];
    const float* w_attn = (const float*)d_in[2];
    const float* w_proj = (const float*)d_in[3];
    float* out = (float*)d_out;

    float *qkvp, *attyp, *xbp, *wabp, *wpbp;
    cudaGetSymbolAddress((void**)&qkvp, g_qkv);
    cudaGetSymbolAddress((void**)&attyp, g_atty);
    cudaGetSymbolAddress((void**)&xbp, g_xb);
    cudaGetSymbolAddress((void**)&wabp, g_wab);
    cudaGetSymbolAddress((void**)&wpbp, g_wpb);

    const int ASMEM = (2*64*KST + 64*VST + 128*KST + 128) * 4;  // 88,576 B -> 2 CTAs/SM
    cudaFuncSetAttribute(attn_mma, cudaFuncAttributeMaxDynamicSharedMemorySize, ASMEM);
    const int GSMEM = 3*GSTAGE_W*4;  // 107,520 B (3-stage)
    cudaFuncSetAttribute(gemm_tf32<true>,  cudaFuncAttributeMaxDynamicSharedMemorySize, GSMEM);
    cudaFuncSetAttribute(gemm_tf32<false>, cudaFuncAttributeMaxDynamicSharedMemorySize, GSMEM);

    // 0) pre-convert inputs to tf32 bits
    cvt_tf32_kernel<<<(BB*TT*CC/4 + 255)/256, 256>>>((const float4*)x, (float4*)xbp, BB*TT*CC/4);
    cvt_tf32_kernel<<<(CC*C3/4 + 255)/256, 256>>>((const float4*)w_attn, (float4*)wabp, CC*C3/4);
    cvt_tf32_kernel<<<(CC*CC/4 + 255)/256, 256>>>((const float4*)w_proj, (float4*)wpbp, CC*CC/4);
    // 1) qkv = x @ w_attn (tf32 bits in/out)
    gemm_tf32<true><<<dim3(C3/128, (BB*TT)/128), 256, GSMEM>>>(
        (const unsigned int*)xbp, (const unsigned int*)wabp, qkvp, BB*TT, C3, CC);
    // 2) zero importance accumulator
    zero_imp_kernel<<<(BB*TT + 255)/256, 256>>>();
    // 3) attention + importance
    attn_mma<<<dim3(TT/128, HH, BB), 256, ASMEM>>>(amask);
    // 4) importance -> d_out tail
    finalize_imp_kernel<<<(BB*TT + 255)/256, 256>>>(out + (size_t)BB*TT*CC);
    // 5) y = atty @ w_proj -> d_out head (fp32 out)
    gemm_tf32<false><<<dim3(CC/128, (BB*TT)/128), 256, GSMEM>>>(
        (const unsigned int*)attyp, (const unsigned int*)wpbp, out, BB*TT, CC, CC);
}

// round 13
// speedup vs baseline: 1.6607x; 1.6607x over previous
#include <cuda_runtime.h>
#include <cuda_fp16.h>
#include <stdint.h>
#include <math.h>

#define BB 4
#define TT 2048
#define CC 768
#define HH 12
#define HS 64
#define C3 (3*CC)

// ---------------- scratch (static device globals; no allocations) ----------------
__device__ __half g_qkvh[(size_t)BB*TT*C3];    // (B,T,3C) half
__device__ __half g_vt[(size_t)BB*HH*HS*TT];   // V transposed: [(b,h,d)][T] half
__device__ __half g_atty[(size_t)BB*TT*CC];    // attention out, half
__device__ __half g_xh[(size_t)BB*TT*CC];      // x as half
__device__ __half g_wah[(size_t)C3*CC];        // w_attn^T [3C][C] half
__device__ __half g_wph[(size_t)CC*CC];        // w_proj^T [C][C] half
__device__ float  g_imp[BB*TT];                // importance accumulator

// ---------------- helpers ----------------------------------------------------------
__device__ __forceinline__ float ex2f(float x) {
    float r;
    asm("ex2.approx.f32 %0, %1;" : "=f"(r) : "f"(x));
    return r;
}

__device__ __forceinline__ unsigned int pk2(float a, float b) {
    __half2 h = __floats2half2_rn(a, b);
    return *(unsigned int*)&h;
}

__device__ __forceinline__ void mma_f16(float c[4], const unsigned int a[4], const unsigned int b[2]) {
    asm volatile(
        "mma.sync.aligned.m16n8k16.row.col.f32.f16.f16.f32 "
        "{%0,%1,%2,%3}, {%4,%5,%6,%7}, {%8,%9}, {%0,%1,%2,%3};"
        : "+f"(c[0]), "+f"(c[1]), "+f"(c[2]), "+f"(c[3])
        : "r"(a[0]), "r"(a[1]), "r"(a[2]), "r"(a[3]), "r"(b[0]), "r"(b[1]));
}

__device__ __forceinline__ void cp16(void* smem_ptr, const void* gptr) {
    unsigned int sa = (unsigned int)__cvta_generic_to_shared(smem_ptr);
    asm volatile("cp.async.cg.shared.global [%0], [%1], 16;\n" :: "r"(sa), "l"(gptr));
}
#define CP_COMMIT() asm volatile("cp.async.commit_group;\n")
#define CP_WAIT1()  asm volatile("cp.async.wait_group 1;\n")
#define CP_WAIT0()  asm volatile("cp.async.wait_group 0;\n")

#define C1SC 0.18033688f   // 0.125 * log2(e)

// ---------------- fp32 -> half elementwise ------------------------------------------
__global__ void cvt_h_kernel(const float4* __restrict__ src, uint2* __restrict__ dst, int n4) {
    int i = blockIdx.x*256 + threadIdx.x;
    if (i < n4) {
        float4 v = src[i];
        uint2 o;
        o.x = pk2(v.x, v.y);
        o.y = pk2(v.z, v.w);
        dst[i] = o;
    }
}

// ---------------- transpose + cvt: WT[n][k] = half(W[k][n]) -------------------------
__global__ void transpose_h_kernel(const float* __restrict__ W, __half* __restrict__ WT,
                                   int K, int N) {
    __shared__ float tile[32][33];
    int k0 = blockIdx.x*32, n0 = blockIdx.y*32;
    int tx = threadIdx.x, ty = threadIdx.y;
    #pragma unroll
    for (int i = ty; i < 32; i += 8)
        tile[i][tx] = W[(size_t)(k0+i)*N + n0 + tx];
    __syncthreads();
    #pragma unroll
    for (int i = ty; i < 32; i += 8)
        WT[(size_t)(n0+i)*K + k0 + tx] = __float2half_rn(tile[tx][i]);
}

// ---------------- transpose V slice of qkv into g_vt --------------------------------
__global__ void transpose_v_kernel() {
    __shared__ __half tile[32][33];
    int bh = blockIdx.z;
    int b = bh / HH, h = bh % HH;
    int t0 = blockIdx.x*32, d0 = blockIdx.y*32;
    int tx = threadIdx.x, ty = threadIdx.y;
    const __half* src = g_qkvh + (size_t)(b*TT + t0)*C3 + 2*CC + h*HS + d0;
    #pragma unroll
    for (int i = ty; i < 32; i += 8)
        tile[i][tx] = src[(size_t)i*C3 + tx];
    __syncthreads();
    __half* dst = g_vt + ((size_t)(b*HH + h)*HS + d0)*TT + t0;
    #pragma unroll
    for (int i = ty; i < 32; i += 8)
        dst[(size_t)i*TT + tx] = tile[tx][i];
}

// ---------------- fp16 tensor-core GEMM: C[M,N] = A[M,K] * Bt[N,K]^T ---------------
// 128x128x64 tile, 256 thr, 3-stage cp.async pipeline, one sync per k-tile.
#define GRS 72                 // row stride in halves (144B) -> conflict-free frags
#define GTILEH (128*GRS)       // halves per tile

template<int HOUT>
__global__ __launch_bounds__(256, 2) void gemm_f16(
        const __half* __restrict__ A, const __half* __restrict__ Bt,
        void* __restrict__ Cout, int M, int N, int K) {
    extern __shared__ __half gsh[];   // [3][2][GTILEH]

    int tid = threadIdx.x;
    int lane = tid & 31, warp = tid >> 5;
    int wm = warp >> 2, wn = warp & 3;
    int g = lane >> 2, t = lane & 3;
    int m0 = blockIdx.y*128, n0 = blockIdx.x*128;
    int nkt = K / 64;

    float acc[4][4][4];
    #pragma unroll
    for (int i = 0; i < 4; i++)
        #pragma unroll
        for (int j = 0; j < 4; j++)
            #pragma unroll
            for (int r = 0; r < 4; r++) acc[i][j][r] = 0.f;

    auto stage = [&](int kt, int s) {
        __half* Ad = gsh + s*2*GTILEH;
        __half* Bd = Ad + GTILEH;
        #pragma unroll
        for (int i = 0; i < 4; i++) {
            int idx = tid + i*256;          // 0..1023
            int r = idx >> 3, c8 = (idx & 7)*8;
            cp16(Ad + r*GRS + c8, A + (size_t)(m0+r)*K + kt*64 + c8);
            cp16(Bd + r*GRS + c8, Bt + (size_t)(n0+r)*K + kt*64 + c8);
        }
    };

    stage(0, 0); CP_COMMIT();
    stage(1, 1); CP_COMMIT();

    for (int kt = 0; kt < nkt; kt++) {
        CP_WAIT1();
        __syncthreads();
        if (kt + 2 < nkt) stage(kt+2, (kt+2)%3);
        CP_COMMIT();

        const __half* Ab = gsh + (kt%3)*2*GTILEH;
        const __half* Bb = Ab + GTILEH;

        #pragma unroll
        for (int ks = 0; ks < 4; ks++) {
            int k = ks*16;
            unsigned int af[4][4];
            #pragma unroll
            for (int mt = 0; mt < 4; mt++) {
                int r0 = wm*64 + mt*16;
                af[mt][0] = *(const unsigned int*)&Ab[(r0+g)*GRS + k + 2*t];
                af[mt][1] = *(const unsigned int*)&Ab[(r0+g+8)*GRS + k + 2*t];
                af[mt][2] = *(const unsigned int*)&Ab[(r0+g)*GRS + k + 2*t + 8];
                af[mt][3] = *(const unsigned int*)&Ab[(r0+g+8)*GRS + k + 2*t + 8];
            }
            unsigned int bf[4][2];
            #pragma unroll
            for (int nt = 0; nt < 4; nt++) {
                int c0 = wn*32 + nt*8 + g;
                bf[nt][0] = *(const unsigned int*)&Bb[c0*GRS + k + 2*t];
                bf[nt][1] = *(const unsigned int*)&Bb[c0*GRS + k + 2*t + 8];
            }
            #pragma unroll
            for (int mt = 0; mt < 4; mt++)
                #pragma unroll
                for (int nt = 0; nt < 4; nt++)
                    mma_f16(acc[mt][nt], af[mt], bf[nt]);
        }
    }

    #pragma unroll
    for (int mt = 0; mt < 4; mt++) {
        int r = m0 + wm*64 + mt*16 + g;
        #pragma unroll
        for (int nt = 0; nt < 4; nt++) {
            int c = n0 + wn*32 + nt*8 + 2*t;
            if (HOUT) {
                __half* Ch = (__half*)Cout;
                *(unsigned int*)&Ch[(size_t)r*N + c]     = pk2(acc[mt][nt][0], acc[mt][nt][1]);
                *(unsigned int*)&Ch[(size_t)(r+8)*N + c] = pk2(acc[mt][nt][2], acc[mt][nt][3]);
            } else {
                float* Cf = (float*)Cout;
                *(float2*)&Cf[(size_t)r*N + c]     = make_float2(acc[mt][nt][0], acc[mt][nt][1]);
                *(float2*)&Cf[(size_t)(r+8)*N + c] = make_float2(acc[mt][nt][2], acc[mt][nt][3]);
            }
        }
    }
}

// ---------------- fp16 mma attention: grid (T/128, H, B), block 256 (8 warps) ------
// Two-pass flash (R9 structure), fp16 operands, fp32 accum/softmax.
#define KST 72   // halves per row (144B)
#define VST 72

__device__ __forceinline__ void stageK(__half* dst, const __half* src, int tid) {
    #pragma unroll
    for (int i = tid; i < 512; i += 256) {
        int r = i >> 3, c8 = (i & 7)*8;
        cp16(dst + r*KST + c8, src + (size_t)r*C3 + c8);
    }
}

__device__ __forceinline__ void stageV(__half* dst, const __half* src, int tid) {
    #pragma unroll
    for (int i = tid; i < 512; i += 256) {
        int r = i >> 3, c8 = (i & 7)*8;
        cp16(dst + r*VST + c8, src + (size_t)r*TT + c8);
    }
}

__global__ __launch_bounds__(256, 2) void attn_mma(const int* __restrict__ amask) {
    extern __shared__ __half smh[];
    __half* Ks = smh;                      // [2][64*KST]
    __half* Vs = smh + 2*64*KST;           // [2][64*VST]
    __half* Ps = Vs + 2*64*VST;            // [128*KST] (Q staging, then P)
    float* kvl = (float*)(Ps + 128*KST);   // [2][64] additive key mask

    const int tid = threadIdx.x;
    const int lane = tid & 31, warp = tid >> 5;
    const int g = lane >> 2, t = lane & 3;
    const int qt = (TT/128 - 1) - blockIdx.x;
    const int h = blockIdx.y, b = blockIdx.z;
    const int qbase = qt*128;
    const int nkt = 2*qt + 2;

    const __half* qsrc = g_qkvh + (size_t)(b*TT+qbase)*C3 + h*HS;
    const __half* kall = g_qkvh + (size_t)(b*TT)*C3 + CC + h*HS;
    const __half* vtall = g_vt + (size_t)(b*HH + h)*HS*TT;

    const int wrow0 = qbase + warp*16;
    const int gr0 = wrow0 + g;
    const int gr1 = gr0 + 8;

    // ---- prologue: stage Q (128 rows) -> Ps and K0 -> Ks[0] ----
    #pragma unroll
    for (int i = tid; i < 1024; i += 256) {
        int r = i >> 3, c8 = (i & 7)*8;
        cp16(Ps + r*KST + c8, qsrc + (size_t)r*C3 + c8);
    }
    stageK(Ks, kall, tid);
    if (tid < 64) kvl[tid] = amask[b*TT + tid] ? 0.f : -1e30f;
    CP_COMMIT();
    CP_WAIT0();
    __syncthreads();

    unsigned int qa[4][4];
    const int qrow = warp*16 + g;
    #pragma unroll
    for (int c = 0; c < 4; c++) {
        qa[c][0] = *(const unsigned int*)&Ps[qrow*KST + 16*c + 2*t];
        qa[c][1] = *(const unsigned int*)&Ps[(qrow+8)*KST + 16*c + 2*t];
        qa[c][2] = *(const unsigned int*)&Ps[qrow*KST + 16*c + 2*t + 8];
        qa[c][3] = *(const unsigned int*)&Ps[(qrow+8)*KST + 16*c + 2*t + 8];
    }

    float l0 = 0.f, l1 = 0.f;

    // ================= Pass A: row sums =================
    for (int kt = 0; kt < nkt; kt++) {
        const int kbase = kt*64;
        CP_WAIT0();
        __syncthreads();
        if (kt + 1 < nkt) {
            stageK(Ks + ((kt+1)&1)*64*KST, kall + (size_t)(kbase+64)*C3, tid);
            if (tid < 64) kvl[((kt+1)&1)*64 + tid] = amask[b*TT + kbase+64 + tid] ? 0.f : -1e30f;
        }
        CP_COMMIT();

        const __half* K0 = Ks + (kt&1)*64*KST;
        const float* kv = kvl + (kt&1)*64;

        float s[8][4];
        #pragma unroll
        for (int j = 0; j < 8; j++) { s[j][0]=s[j][1]=s[j][2]=s[j][3]=0.f; }
        #pragma unroll
        for (int c = 0; c < 4; c++) {
            #pragma unroll
            for (int j = 0; j < 8; j++) {
                unsigned int bf[2];
                bf[0] = *(const unsigned int*)&K0[(8*j+g)*KST + 16*c + 2*t];
                bf[1] = *(const unsigned int*)&K0[(8*j+g)*KST + 16*c + 2*t + 8];
                mma_f16(s[j], qa[c], bf);
            }
        }
        float ts0 = 0.f, ts1 = 0.f;
        if (kbase + 63 <= wrow0) {   // interior
            #pragma unroll
            for (int j = 0; j < 8; j++) {
                float kv0 = kv[8*j+2*t], kv1 = kv[8*j+2*t+1];
                ts0 += ex2f(fmaf(s[j][0], C1SC, kv0)) + ex2f(fmaf(s[j][1], C1SC, kv1));
                ts1 += ex2f(fmaf(s[j][2], C1SC, kv0)) + ex2f(fmaf(s[j][3], C1SC, kv1));
            }
        } else {                     // diagonal
            #pragma unroll
            for (int j = 0; j < 8; j++) {
                int c0 = kbase + 8*j + 2*t;
                float kv0 = kv[8*j+2*t], kv1 = kv[8*j+2*t+1];
                float v0 = fmaf(s[j][0], C1SC, kv0); if (c0   > gr0) v0 = -1e30f;
                float v1 = fmaf(s[j][1], C1SC, kv1); if (c0+1 > gr0) v1 = -1e30f;
                float v2 = fmaf(s[j][2], C1SC, kv0); if (c0   > gr1) v2 = -1e30f;
                float v3 = fmaf(s[j][3], C1SC, kv1); if (c0+1 > gr1) v3 = -1e30f;
                ts0 += ex2f(v0) + ex2f(v1);
                ts1 += ex2f(v2) + ex2f(v3);
            }
        }
        ts0 += __shfl_xor_sync(0xffffffffu, ts0, 1);
        ts0 += __shfl_xor_sync(0xffffffffu, ts0, 2);
        ts1 += __shfl_xor_sync(0xffffffffu, ts1, 1);
        ts1 += __shfl_xor_sync(0xffffffffu, ts1, 2);
        l0 += ts0;
        l1 += ts1;
    }
    const float li0 = 1.0f/l0, li1 = 1.0f/l1;

    // ================= Pass B: output + importance =================
    float o[8][4];
    #pragma unroll
    for (int j = 0; j < 8; j++) { o[j][0]=o[j][1]=o[j][2]=o[j][3]=0.f; }

    __syncthreads();
    stageK(Ks, kall, tid);
    stageV(Vs, vtall, tid);
    if (tid < 64) kvl[tid] = amask[b*TT + tid] ? 0.f : -1e30f;
    CP_COMMIT();

    for (int kt = 0; kt < nkt; kt++) {
        const int kbase = kt*64;
        CP_WAIT0();
        __syncthreads();
        if (kt + 1 < nkt) {
            stageK(Ks + ((kt+1)&1)*64*KST, kall + (size_t)(kbase+64)*C3, tid);
            stageV(Vs + ((kt+1)&1)*64*VST, vtall + kbase + 64, tid);
            if (tid < 64) kvl[((kt+1)&1)*64 + tid] = amask[b*TT + kbase+64 + tid] ? 0.f : -1e30f;
        }
        CP_COMMIT();

        const __half* K0 = Ks + (kt&1)*64*KST;
        const __half* V0 = Vs + (kt&1)*64*VST;
        const float* kv = kvl + (kt&1)*64;

        float s[8][4];
        #pragma unroll
        for (int j = 0; j < 8; j++) { s[j][0]=s[j][1]=s[j][2]=s[j][3]=0.f; }
        #pragma unroll
        for (int c = 0; c < 4; c++) {
            #pragma unroll
            for (int j = 0; j < 8; j++) {
                unsigned int bf[2];
                bf[0] = *(const unsigned int*)&K0[(8*j+g)*KST + 16*c + 2*t];
                bf[1] = *(const unsigned int*)&K0[(8*j+g)*KST + 16*c + 2*t + 8];
                mma_f16(s[j], qa[c], bf);
            }
        }
        const bool interior = (kbase + 63 <= wrow0);
        float* imp_base = &g_imp[b*TT + kbase];
        #pragma unroll
        for (int j = 0; j < 8; j++) {
            int c0 = kbase + 8*j + 2*t;
            float kv0 = kv[8*j+2*t], kv1 = kv[8*j+2*t+1];
            float v0 = fmaf(s[j][0], C1SC, kv0);
            float v1 = fmaf(s[j][1], C1SC, kv1);
            float v2 = fmaf(s[j][2], C1SC, kv0);
            float v3 = fmaf(s[j][3], C1SC, kv1);
            if (!interior) {
                if (c0   > gr0) v0 = -1e30f;
                if (c0+1 > gr0) v1 = -1e30f;
                if (c0   > gr1) v2 = -1e30f;
                if (c0+1 > gr1) v3 = -1e30f;
            }
            float p0 = ex2f(v0) * li0;
            float p1 = ex2f(v1) * li0;
            float p2 = ex2f(v2) * li1;
            float p3 = ex2f(v3) * li1;
            *(unsigned int*)&Ps[(warp*16+g)*KST   + 8*j + 2*t] = pk2(p0, p1);
            *(unsigned int*)&Ps[(warp*16+g+8)*KST + 8*j + 2*t] = pk2(p2, p3);
            float cA = p0 + p2;
            float cB = p1 + p3;
            cA += __shfl_xor_sync(0xffffffffu, cA, 4);
            cA += __shfl_xor_sync(0xffffffffu, cA, 8);
            cA += __shfl_xor_sync(0xffffffffu, cA, 16);
            cB += __shfl_xor_sync(0xffffffffu, cB, 4);
            cB += __shfl_xor_sync(0xffffffffu, cB, 8);
            cB += __shfl_xor_sync(0xffffffffu, cB, 16);
            if (g == 0) {
                atomicAdd(imp_base + 8*j + 2*t,     cA);
                atomicAdd(imp_base + 8*j + 2*t + 1, cB);
            }
        }
        // O += P @ V (Vt layout: rows d, cols key)
        #pragma unroll
        for (int c = 0; c < 4; c++) {
            unsigned int pa[4];
            pa[0] = *(const unsigned int*)&Ps[(warp*16+g)*KST   + 16*c + 2*t];
            pa[1] = *(const unsigned int*)&Ps[(warp*16+g+8)*KST + 16*c + 2*t];
            pa[2] = *(const unsigned int*)&Ps[(warp*16+g)*KST   + 16*c + 2*t + 8];
            pa[3] = *(const unsigned int*)&Ps[(warp*16+g+8)*KST + 16*c + 2*t + 8];
            #pragma unroll
            for (int j = 0; j < 8; j++) {
                unsigned int bv[2];
                bv[0] = *(const unsigned int*)&V0[(8*j+g)*VST + 16*c + 2*t];
                bv[1] = *(const unsigned int*)&V0[(8*j+g)*VST + 16*c + 2*t + 8];
                mma_f16(o[j], pa, bv);
            }
        }
    }

    // write O to g_atty (half)
    __half* ydst = g_atty + (size_t)(b*TT)*CC + h*HS;
    #pragma unroll
    for (int j = 0; j < 8; j++) {
        int col = 8*j + 2*t;
        *(unsigned int*)&ydst[(size_t)gr0*CC + col] = pk2(o[j][0], o[j][1]);
        *(unsigned int*)&ydst[(size_t)gr1*CC + col] = pk2(o[j][2], o[j][3]);
    }
}

__global__ void zero_imp_kernel() {
    int i = blockIdx.x*256 + threadIdx.x;
    if (i < BB*TT) g_imp[i] = 0.f;
}

__global__ void finalize_imp_kernel(float* __restrict__ out) {
    int i = blockIdx.x*256 + threadIdx.x;
    if (i < BB*TT) out[i] = g_imp[i] * (1.0f / (HH * (float)TT));
}

extern "C" void kernel_launch(void* const* d_in, const int* in_sizes, int n_in,
                              void* d_out, int out_size) {
    const float* x      = (const float*)d_in[0];
    const int*   amask  = (const int*)d_in[1];
    const float* w_attn = (const float*)d_in[2];
    const float* w_proj = (const float*)d_in[3];
    float* out = (float*)d_out;

    __half *qkvhp, *attyp, *xhp, *wahp, *wphp;
    cudaGetSymbolAddress((void**)&qkvhp, g_qkvh);
    cudaGetSymbolAddress((void**)&attyp, g_atty);
    cudaGetSymbolAddress((void**)&xhp, g_xh);
    cudaGetSymbolAddress((void**)&wahp, g_wah);
    cudaGetSymbolAddress((void**)&wphp, g_wph);

    const int ASMEM = (2*64*KST + 2*64*VST + 128*KST)*2 + 2*64*4;  // 55,808 B
    cudaFuncSetAttribute(attn_mma, cudaFuncAttributeMaxDynamicSharedMemorySize, ASMEM);
    const int GSMEM = 3*2*GTILEH*2;  // 110,592 B
    cudaFuncSetAttribute(gemm_f16<1>, cudaFuncAttributeMaxDynamicSharedMemorySize, GSMEM);
    cudaFuncSetAttribute(gemm_f16<0>, cudaFuncAttributeMaxDynamicSharedMemorySize, GSMEM);

    // 0) convert x to half; transpose+convert weights
    cvt_h_kernel<<<(BB*TT*CC/4 + 255)/256, 256>>>((const float4*)x, (uint2*)xhp, BB*TT*CC/4);
    transpose_h_kernel<<<dim3(CC/32, C3/32), dim3(32,8)>>>(w_attn, wahp, CC, C3);
    transpose_h_kernel<<<dim3(CC/32, CC/32), dim3(32,8)>>>(w_proj, wphp, CC, CC);
    // 1) qkv = x @ w_attn (fp16 in/out, fp32 accumulate)
    gemm_f16<1><<<dim3(C3/128, (BB*TT)/128), 256, GSMEM>>>(xhp, wahp, qkvhp, BB*TT, C3, CC);
    // 2) transpose V per (b,h) into g_vt
    transpose_v_kernel<<<dim3(TT/32, HS/32, BB*HH), dim3(32,8)>>>();
    // 3) zero importance accumulator
    zero_imp_kernel<<<(BB*TT + 255)/256, 256>>>();
    // 4) attention + importance (fp16 mma)
    attn_mma<<<dim3(TT/128, HH, BB), 256, ASMEM>>>(amask);
    // 5) importance -> d_out tail
    finalize_imp_kernel<<<(BB*TT + 255)/256, 256>>>(out + (size_t)BB*TT*CC);
    // 6) y = atty @ w_proj -> d_out head (fp32 out)
    gemm_f16<0><<<dim3(CC/128, (BB*TT)/128), 256, GSMEM>>>(attyp, wphp, out, BB*TT, CC, CC);
}

// round 14
// speedup vs baseline: 1.7011x; 1.0243x over previous
#include <cuda_runtime.h>
#include <cuda_fp16.h>
#include <stdint.h>
#include <math.h>

#define BB 4
#define TT 2048
#define CC 768
#define HH 12
#define HS 64
#define C3 (3*CC)

// ---------------- scratch (static device globals; no allocations) ----------------
__device__ __half g_qkvh[(size_t)BB*TT*C3];    // (B,T,3C) half
__device__ __half g_vt[(size_t)BB*HH*HS*TT];   // V transposed: [(b,h,d)][T] half
__device__ __half g_atty[(size_t)BB*TT*CC];    // attention out, half
__device__ __half g_xh[(size_t)BB*TT*CC];      // x as half
__device__ __half g_wah[(size_t)C3*CC];        // w_attn^T [3C][C] half
__device__ __half g_wph[(size_t)CC*CC];        // w_proj^T [C][C] half
__device__ float  g_imp[BB*TT];                // importance accumulator

// ---------------- helpers ----------------------------------------------------------
__device__ __forceinline__ float ex2f(float x) {
    float r;
    asm("ex2.approx.f32 %0, %1;" : "=f"(r) : "f"(x));
    return r;
}

__device__ __forceinline__ unsigned int pk2(float a, float b) {
    __half2 h = __floats2half2_rn(a, b);
    return *(unsigned int*)&h;
}

__device__ __forceinline__ void mma_f16(float c[4], const unsigned int a[4], const unsigned int b[2]) {
    asm volatile(
        "mma.sync.aligned.m16n8k16.row.col.f32.f16.f16.f32 "
        "{%0,%1,%2,%3}, {%4,%5,%6,%7}, {%8,%9}, {%0,%1,%2,%3};"
        : "+f"(c[0]), "+f"(c[1]), "+f"(c[2]), "+f"(c[3])
        : "r"(a[0]), "r"(a[1]), "r"(a[2]), "r"(a[3]), "r"(b[0]), "r"(b[1]));
}

__device__ __forceinline__ void ldsm_x4(unsigned int r[4], const void* p) {
    unsigned int a = (unsigned int)__cvta_generic_to_shared(p);
    asm volatile("ldmatrix.sync.aligned.m8n8.x4.shared.b16 {%0,%1,%2,%3}, [%4];"
        : "=r"(r[0]), "=r"(r[1]), "=r"(r[2]), "=r"(r[3]) : "r"(a));
}

__device__ __forceinline__ void ldsm_x2(unsigned int r[2], const void* p) {
    unsigned int a = (unsigned int)__cvta_generic_to_shared(p);
    asm volatile("ldmatrix.sync.aligned.m8n8.x2.shared.b16 {%0,%1}, [%2];"
        : "=r"(r[0]), "=r"(r[1]) : "r"(a));
}

__device__ __forceinline__ void cp16(void* smem_ptr, const void* gptr) {
    unsigned int sa = (unsigned int)__cvta_generic_to_shared(smem_ptr);
    asm volatile("cp.async.cg.shared.global [%0], [%1], 16;\n" :: "r"(sa), "l"(gptr));
}
#define CP_COMMIT() asm volatile("cp.async.commit_group;\n")
#define CP_WAIT1()  asm volatile("cp.async.wait_group 1;\n")
#define CP_WAIT0()  asm volatile("cp.async.wait_group 0;\n")

#define C1SC 0.18033688f   // 0.125 * log2(e)

// ---------------- fp32 -> half elementwise ------------------------------------------
__global__ void cvt_h_kernel(const float4* __restrict__ src, uint2* __restrict__ dst, int n4) {
    int i = blockIdx.x*256 + threadIdx.x;
    if (i < n4) {
        float4 v = src[i];
        uint2 o;
        o.x = pk2(v.x, v.y);
        o.y = pk2(v.z, v.w);
        dst[i] = o;
    }
}

// ---------------- transpose + cvt: WT[n][k] = half(W[k][n]) -------------------------
__global__ void transpose_h_kernel(const float* __restrict__ W, __half* __restrict__ WT,
                                   int K, int N) {
    __shared__ float tile[32][33];
    int k0 = blockIdx.x*32, n0 = blockIdx.y*32;
    int tx = threadIdx.x, ty = threadIdx.y;
    #pragma unroll
    for (int i = ty; i < 32; i += 8)
        tile[i][tx] = W[(size_t)(k0+i)*N + n0 + tx];
    __syncthreads();
    #pragma unroll
    for (int i = ty; i < 32; i += 8)
        WT[(size_t)(n0+i)*K + k0 + tx] = __float2half_rn(tile[tx][i]);
}

// ---------------- transpose V slice of qkv into g_vt --------------------------------
__global__ void transpose_v_kernel() {
    __shared__ __half tile[32][33];
    int bh = blockIdx.z;
    int b = bh / HH, h = bh % HH;
    int t0 = blockIdx.x*32, d0 = blockIdx.y*32;
    int tx = threadIdx.x, ty = threadIdx.y;
    const __half* src = g_qkvh + (size_t)(b*TT + t0)*C3 + 2*CC + h*HS + d0;
    #pragma unroll
    for (int i = ty; i < 32; i += 8)
        tile[i][tx] = src[(size_t)i*C3 + tx];
    __syncthreads();
    __half* dst = g_vt + ((size_t)(b*HH + h)*HS + d0)*TT + t0;
    #pragma unroll
    for (int i = ty; i < 32; i += 8)
        dst[(size_t)i*TT + tx] = tile[tx][i];
}

// ---------------- fp16 tensor-core GEMM: C[M,N] = A[M,K] * Bt[N,K]^T ---------------
// 128x128x64 tile, 256 thr, 3-stage cp.async pipeline, ldmatrix fragment loads.
#define GRS 72                 // row stride in halves (144B) -> conflict-free ldmatrix
#define GTILEH (128*GRS)       // halves per tile

template<int HOUT>
__global__ __launch_bounds__(256, 2) void gemm_f16(
        const __half* __restrict__ A, const __half* __restrict__ Bt,
        void* __restrict__ Cout, int M, int N, int K) {
    extern __shared__ __half gsh[];   // [3][2][GTILEH]

    int tid = threadIdx.x;
    int lane = tid & 31, warp = tid >> 5;
    int wm = warp >> 2, wn = warp & 3;
    int g = lane >> 2, t = lane & 3;
    int m0 = blockIdx.y*128, n0 = blockIdx.x*128;
    int nkt = K / 64;

    // ldmatrix per-lane row/col selectors
    const int a_lr = wm*64 + (lane & 15);        // + mt*16
    const int a_lc = (lane >> 4) * 8;            // 0 or 8 (k offset)
    const int b_lr = lane & 7;                   // + c0
    const int b_lc = ((lane >> 3) & 1) * 8;      // 0 or 8

    float acc[4][4][4];
    #pragma unroll
    for (int i = 0; i < 4; i++)
        #pragma unroll
        for (int j = 0; j < 4; j++)
            #pragma unroll
            for (int r = 0; r < 4; r++) acc[i][j][r] = 0.f;

    auto stage = [&](int kt, int s) {
        __half* Ad = gsh + s*2*GTILEH;
        __half* Bd = Ad + GTILEH;
        #pragma unroll
        for (int i = 0; i < 4; i++) {
            int idx = tid + i*256;          // 0..1023
            int r = idx >> 3, c8 = (idx & 7)*8;
            cp16(Ad + r*GRS + c8, A + (size_t)(m0+r)*K + kt*64 + c8);
            cp16(Bd + r*GRS + c8, Bt + (size_t)(n0+r)*K + kt*64 + c8);
        }
    };

    stage(0, 0); CP_COMMIT();
    stage(1, 1); CP_COMMIT();

    for (int kt = 0; kt < nkt; kt++) {
        CP_WAIT1();
        __syncthreads();
        if (kt + 2 < nkt) stage(kt+2, (kt+2)%3);
        CP_COMMIT();

        const __half* Ab = gsh + (kt%3)*2*GTILEH;
        const __half* Bb = Ab + GTILEH;

        #pragma unroll
        for (int ks = 0; ks < 4; ks++) {
            int k = ks*16;
            unsigned int af[4][4];
            #pragma unroll
            for (int mt = 0; mt < 4; mt++)
                ldsm_x4(af[mt], &Ab[(a_lr + mt*16)*GRS + k + a_lc]);
            unsigned int bf[4][2];
            #pragma unroll
            for (int nt = 0; nt < 4; nt++)
                ldsm_x2(bf[nt], &Bb[(wn*32 + nt*8 + b_lr)*GRS + k + b_lc]);
            #pragma unroll
            for (int mt = 0; mt < 4; mt++)
                #pragma unroll
                for (int nt = 0; nt < 4; nt++)
                    mma_f16(acc[mt][nt], af[mt], bf[nt]);
        }
    }

    #pragma unroll
    for (int mt = 0; mt < 4; mt++) {
        int r = m0 + wm*64 + mt*16 + g;
        #pragma unroll
        for (int nt = 0; nt < 4; nt++) {
            int c = n0 + wn*32 + nt*8 + 2*t;
            if (HOUT) {
                __half* Ch = (__half*)Cout;
                *(unsigned int*)&Ch[(size_t)r*N + c]     = pk2(acc[mt][nt][0], acc[mt][nt][1]);
                *(unsigned int*)&Ch[(size_t)(r+8)*N + c] = pk2(acc[mt][nt][2], acc[mt][nt][3]);
            } else {
                float* Cf = (float*)Cout;
                *(float2*)&Cf[(size_t)r*N + c]     = make_float2(acc[mt][nt][0], acc[mt][nt][1]);
                *(float2*)&Cf[(size_t)(r+8)*N + c] = make_float2(acc[mt][nt][2], acc[mt][nt][3]);
            }
        }
    }
}

// ---------------- fp16 mma attention: grid (T/128, H, B), block 256 (8 warps) ------
// Two-pass flash, fp16 operands, fp32 softmax, ldmatrix fragment loads.
#define KST 72   // halves per row (144B)
#define VST 72

__device__ __forceinline__ void stageK(__half* dst, const __half* src, int tid) {
    #pragma unroll
    for (int i = tid; i < 512; i += 256) {
        int r = i >> 3, c8 = (i & 7)*8;
        cp16(dst + r*KST + c8, src + (size_t)r*C3 + c8);
    }
}

__device__ __forceinline__ void stageV(__half* dst, const __half* src, int tid) {
    #pragma unroll
    for (int i = tid; i < 512; i += 256) {
        int r = i >> 3, c8 = (i & 7)*8;
        cp16(dst + r*VST + c8, src + (size_t)r*TT + c8);
    }
}

__global__ __launch_bounds__(256, 2) void attn_mma(const int* __restrict__ amask) {
    extern __shared__ __half smh[];
    __half* Ks = smh;                      // [2][64*KST]
    __half* Vs = smh + 2*64*KST;           // [2][64*VST]
    __half* Ps = Vs + 2*64*VST;            // [128*KST] (Q staging, then P)
    float* kvl = (float*)(Ps + 128*KST);   // [2][64] additive key mask

    const int tid = threadIdx.x;
    const int lane = tid & 31, warp = tid >> 5;
    const int g = lane >> 2, t = lane & 3;
    const int qt = (TT/128 - 1) - blockIdx.x;
    const int h = blockIdx.y, b = blockIdx.z;
    const int qbase = qt*128;
    const int nkt = 2*qt + 2;

    const __half* qsrc = g_qkvh + (size_t)(b*TT+qbase)*C3 + h*HS;
    const __half* kall = g_qkvh + (size_t)(b*TT)*C3 + CC + h*HS;
    const __half* vtall = g_vt + (size_t)(b*HH + h)*HS*TT;

    const int wrow0 = qbase + warp*16;
    const int gr0 = wrow0 + g;
    const int gr1 = gr0 + 8;

    // ldmatrix per-lane selectors
    const int x4_lr = lane & 15;                 // row within 16-row tile
    const int x4_lc = (lane >> 4) * 8;           // 0 or 8
    const int x2_lr = lane & 7;                  // row within 8-row tile
    const int x2_lc = ((lane >> 3) & 1) * 8;     // 0 or 8

    // ---- prologue: stage Q (128 rows) -> Ps and K0 -> Ks[0] ----
    #pragma unroll
    for (int i = tid; i < 1024; i += 256) {
        int r = i >> 3, c8 = (i & 7)*8;
        cp16(Ps + r*KST + c8, qsrc + (size_t)r*C3 + c8);
    }
    stageK(Ks, kall, tid);
    if (tid < 64) kvl[tid] = amask[b*TT + tid] ? 0.f : -1e30f;
    CP_COMMIT();
    CP_WAIT0();
    __syncthreads();

    unsigned int qa[4][4];
    #pragma unroll
    for (int c = 0; c < 4; c++)
        ldsm_x4(qa[c], &Ps[(warp*16 + x4_lr)*KST + 16*c + x4_lc]);

    float l0 = 0.f, l1 = 0.f;

    // ================= Pass A: row sums =================
    for (int kt = 0; kt < nkt; kt++) {
        const int kbase = kt*64;
        CP_WAIT0();
        __syncthreads();
        if (kt + 1 < nkt) {
            stageK(Ks + ((kt+1)&1)*64*KST, kall + (size_t)(kbase+64)*C3, tid);
            if (tid < 64) kvl[((kt+1)&1)*64 + tid] = amask[b*TT + kbase+64 + tid] ? 0.f : -1e30f;
        }
        CP_COMMIT();

        const __half* K0 = Ks + (kt&1)*64*KST;
        const float* kv = kvl + (kt&1)*64;

        float s[8][4];
        #pragma unroll
        for (int j = 0; j < 8; j++) { s[j][0]=s[j][1]=s[j][2]=s[j][3]=0.f; }
        #pragma unroll
        for (int c = 0; c < 4; c++) {
            #pragma unroll
            for (int j = 0; j < 8; j++) {
                unsigned int bf[2];
                ldsm_x2(bf, &K0[(8*j + x2_lr)*KST + 16*c + x2_lc]);
                mma_f16(s[j], qa[c], bf);
            }
        }
        float ts0 = 0.f, ts1 = 0.f;
        if (kbase + 63 <= wrow0) {   // interior
            #pragma unroll
            for (int j = 0; j < 8; j++) {
                float kv0 = kv[8*j+2*t], kv1 = kv[8*j+2*t+1];
                ts0 += ex2f(fmaf(s[j][0], C1SC, kv0)) + ex2f(fmaf(s[j][1], C1SC, kv1));
                ts1 += ex2f(fmaf(s[j][2], C1SC, kv0)) + ex2f(fmaf(s[j][3], C1SC, kv1));
            }
        } else {                     // diagonal
            #pragma unroll
            for (int j = 0; j < 8; j++) {
                int c0 = kbase + 8*j + 2*t;
                float kv0 = kv[8*j+2*t], kv1 = kv[8*j+2*t+1];
                float v0 = fmaf(s[j][0], C1SC, kv0); if (c0   > gr0) v0 = -1e30f;
                float v1 = fmaf(s[j][1], C1SC, kv1); if (c0+1 > gr0) v1 = -1e30f;
                float v2 = fmaf(s[j][2], C1SC, kv0); if (c0   > gr1) v2 = -1e30f;
                float v3 = fmaf(s[j][3], C1SC, kv1); if (c0+1 > gr1) v3 = -1e30f;
                ts0 += ex2f(v0) + ex2f(v1);
                ts1 += ex2f(v2) + ex2f(v3);
            }
        }
        ts0 += __shfl_xor_sync(0xffffffffu, ts0, 1);
        ts0 += __shfl_xor_sync(0xffffffffu, ts0, 2);
        ts1 += __shfl_xor_sync(0xffffffffu, ts1, 1);
        ts1 += __shfl_xor_sync(0xffffffffu, ts1, 2);
        l0 += ts0;
        l1 += ts1;
    }
    const float li0 = 1.0f/l0, li1 = 1.0f/l1;

    // ================= Pass B: output + importance =================
    float o[8][4];
    #pragma unroll
    for (int j = 0; j < 8; j++) { o[j][0]=o[j][1]=o[j][2]=o[j][3]=0.f; }

    __syncthreads();
    stageK(Ks, kall, tid);
    stageV(Vs, vtall, tid);
    if (tid < 64) kvl[tid] = amask[b*TT + tid] ? 0.f : -1e30f;
    CP_COMMIT();

    for (int kt = 0; kt < nkt; kt++) {
        const int kbase = kt*64;
        CP_WAIT0();
        __syncthreads();
        if (kt + 1 < nkt) {
            stageK(Ks + ((kt+1)&1)*64*KST, kall + (size_t)(kbase+64)*C3, tid);
            stageV(Vs + ((kt+1)&1)*64*VST, vtall + kbase + 64, tid);
            if (tid < 64) kvl[((kt+1)&1)*64 + tid] = amask[b*TT + kbase+64 + tid] ? 0.f : -1e30f;
        }
        CP_COMMIT();

        const __half* K0 = Ks + (kt&1)*64*KST;
        const __half* V0 = Vs + (kt&1)*64*VST;
        const float* kv = kvl + (kt&1)*64;

        float s[8][4];
        #pragma unroll
        for (int j = 0; j < 8; j++) { s[j][0]=s[j][1]=s[j][2]=s[j][3]=0.f; }
        #pragma unroll
        for (int c = 0; c < 4; c++) {
            #pragma unroll
            for (int j = 0; j < 8; j++) {
                unsigned int bf[2];
                ldsm_x2(bf, &K0[(8*j + x2_lr)*KST + 16*c + x2_lc]);
                mma_f16(s[j], qa[c], bf);
            }
        }
        const bool interior = (kbase + 63 <= wrow0);
        float* imp_base = &g_imp[b*TT + kbase];
        #pragma unroll
        for (int j = 0; j < 8; j++) {
            int c0 = kbase + 8*j + 2*t;
            float kv0 = kv[8*j+2*t], kv1 = kv[8*j+2*t+1];
            float v0 = fmaf(s[j][0], C1SC, kv0);
            float v1 = fmaf(s[j][1], C1SC, kv1);
            float v2 = fmaf(s[j][2], C1SC, kv0);
            float v3 = fmaf(s[j][3], C1SC, kv1);
            if (!interior) {
                if (c0   > gr0) v0 = -1e30f;
                if (c0+1 > gr0) v1 = -1e30f;
                if (c0   > gr1) v2 = -1e30f;
                if (c0+1 > gr1) v3 = -1e30f;
            }
            float p0 = ex2f(v0) * li0;
            float p1 = ex2f(v1) * li0;
            float p2 = ex2f(v2) * li1;
            float p3 = ex2f(v3) * li1;
            *(unsigned int*)&Ps[(warp*16+g)*KST   + 8*j + 2*t] = pk2(p0, p1);
            *(unsigned int*)&Ps[(warp*16+g+8)*KST + 8*j + 2*t] = pk2(p2, p3);
            float cA = p0 + p2;
            float cB = p1 + p3;
            cA += __shfl_xor_sync(0xffffffffu, cA, 4);
            cA += __shfl_xor_sync(0xffffffffu, cA, 8);
            cA += __shfl_xor_sync(0xffffffffu, cA, 16);
            cB += __shfl_xor_sync(0xffffffffu, cB, 4);
            cB += __shfl_xor_sync(0xffffffffu, cB, 8);
            cB += __shfl_xor_sync(0xffffffffu, cB, 16);
            if (g == 0) {
                atomicAdd(imp_base + 8*j + 2*t,     cA);
                atomicAdd(imp_base + 8*j + 2*t + 1, cB);
            }
        }
        // O += P @ V (Vt layout: rows d, cols key)
        #pragma unroll
        for (int c = 0; c < 4; c++) {
            unsigned int pa[4];
            ldsm_x4(pa, &Ps[(warp*16 + x4_lr)*KST + 16*c + x4_lc]);
            #pragma unroll
            for (int j = 0; j < 8; j++) {
                unsigned int bv[2];
                ldsm_x2(bv, &V0[(8*j + x2_lr)*VST + 16*c + x2_lc]);
                mma_f16(o[j], pa, bv);
            }
        }
    }

    // write O to g_atty (half)
    __half* ydst = g_atty + (size_t)(b*TT)*CC + h*HS;
    #pragma unroll
    for (int j = 0; j < 8; j++) {
        int col = 8*j + 2*t;
        *(unsigned int*)&ydst[(size_t)gr0*CC + col] = pk2(o[j][0], o[j][1]);
        *(unsigned int*)&ydst[(size_t)gr1*CC + col] = pk2(o[j][2], o[j][3]);
    }
}

__global__ void zero_imp_kernel() {
    int i = blockIdx.x*256 + threadIdx.x;
    if (i < BB*TT) g_imp[i] = 0.f;
}

__global__ void finalize_imp_kernel(float* __restrict__ out) {
    int i = blockIdx.x*256 + threadIdx.x;
    if (i < BB*TT) out[i] = g_imp[i] * (1.0f / (HH * (float)TT));
}

extern "C" void kernel_launch(void* const* d_in, const int* in_sizes, int n_in,
                              void* d_out, int out_size) {
    const float* x      = (const float*)d_in[0];
    const int*   amask  = (const int*)d_in[1];
    const float* w_attn = (const float*)d_in[2];
    const float* w_proj = (const float*)d_in[3];
    float* out = (float*)d_out;

    __half *qkvhp, *attyp, *xhp, *wahp, *wphp;
    cudaGetSymbolAddress((void**)&qkvhp, g_qkvh);
    cudaGetSymbolAddress((void**)&attyp, g_atty);
    cudaGetSymbolAddress((void**)&xhp, g_xh);
    cudaGetSymbolAddress((void**)&wahp, g_wah);
    cudaGetSymbolAddress((void**)&wphp, g_wph);

    const int ASMEM = (2*64*KST + 2*64*VST + 128*KST)*2 + 2*64*4;  // 55,808 B
    cudaFuncSetAttribute(attn_mma, cudaFuncAttributeMaxDynamicSharedMemorySize, ASMEM);
    const int GSMEM = 3*2*GTILEH*2;  // 110,592 B
    cudaFuncSetAttribute(gemm_f16<1>, cudaFuncAttributeMaxDynamicSharedMemorySize, GSMEM);
    cudaFuncSetAttribute(gemm_f16<0>, cudaFuncAttributeMaxDynamicSharedMemorySize, GSMEM);

    // 0) convert x to half; transpose+convert weights
    cvt_h_kernel<<<(BB*TT*CC/4 + 255)/256, 256>>>((const float4*)x, (uint2*)xhp, BB*TT*CC/4);
    transpose_h_kernel<<<dim3(CC/32, C3/32), dim3(32,8)>>>(w_attn, wahp, CC, C3);
    transpose_h_kernel<<<dim3(CC/32, CC/32), dim3(32,8)>>>(w_proj, wphp, CC, CC);
    // 1) qkv = x @ w_attn (fp16 in/out, fp32 accumulate)
    gemm_f16<1><<<dim3(C3/128, (BB*TT)/128), 256, GSMEM>>>(xhp, wahp, qkvhp, BB*TT, C3, CC);
    // 2) transpose V per (b,h) into g_vt
    transpose_v_kernel<<<dim3(TT/32, HS/32, BB*HH), dim3(32,8)>>>();
    // 3) zero importance accumulator
    zero_imp_kernel<<<(BB*TT + 255)/256, 256>>>();
    // 4) attention + importance (fp16 mma + ldmatrix)
    attn_mma<<<dim3(TT/128, HH, BB), 256, ASMEM>>>(amask);
    // 5) importance -> d_out tail
    finalize_imp_kernel<<<(BB*TT + 255)/256, 256>>>(out + (size_t)BB*TT*CC);
    // 6) y = atty @ w_proj -> d_out head (fp32 out)
    gemm_f16<0><<<dim3(CC/128, (BB*TT)/128), 256, GSMEM>>>(attyp, wphp, out, BB*TT, CC, CC);
}

// round 15
// speedup vs baseline: 1.7490x; 1.0282x over previous
#include <cuda_runtime.h>
#include <cuda_fp16.h>
#include <stdint.h>
#include <math.h>

#define BB 4
#define TT 2048
#define CC 768
#define HH 12
#define HS 64
#define C3 (3*CC)

// ---------------- scratch (static device globals; no allocations) ----------------
__device__ __half g_qkvh[(size_t)BB*TT*C3];    // (B,T,3C) half (v region unused)
__device__ __half g_vt[(size_t)BB*HH*HS*TT];   // V transposed: [(b,h,d)][T] half
__device__ __half g_atty[(size_t)BB*TT*CC];    // attention out, half
__device__ __half g_xh[(size_t)BB*TT*CC];      // x as half
__device__ __half g_wah[(size_t)C3*CC];        // w_attn^T [3C][C] half
__device__ __half g_wph[(size_t)CC*CC];        // w_proj^T [C][C] half
__device__ float  g_imp[BB*TT];                // importance accumulator

// ---------------- helpers ----------------------------------------------------------
__device__ __forceinline__ float ex2f(float x) {
    float r;
    asm("ex2.approx.f32 %0, %1;" : "=f"(r) : "f"(x));
    return r;
}

__device__ __forceinline__ unsigned int pk2(float a, float b) {
    __half2 h = __floats2half2_rn(a, b);
    return *(unsigned int*)&h;
}

__device__ __forceinline__ void mma_f16(float c[4], const unsigned int a[4], const unsigned int b[2]) {
    asm volatile(
        "mma.sync.aligned.m16n8k16.row.col.f32.f16.f16.f32 "
        "{%0,%1,%2,%3}, {%4,%5,%6,%7}, {%8,%9}, {%0,%1,%2,%3};"
        : "+f"(c[0]), "+f"(c[1]), "+f"(c[2]), "+f"(c[3])
        : "r"(a[0]), "r"(a[1]), "r"(a[2]), "r"(a[3]), "r"(b[0]), "r"(b[1]));
}

__device__ __forceinline__ void ldsm_x4(unsigned int r[4], const void* p) {
    unsigned int a = (unsigned int)__cvta_generic_to_shared(p);
    asm volatile("ldmatrix.sync.aligned.m8n8.x4.shared.b16 {%0,%1,%2,%3}, [%4];"
        : "=r"(r[0]), "=r"(r[1]), "=r"(r[2]), "=r"(r[3]) : "r"(a));
}

__device__ __forceinline__ void ldsm_x2(unsigned int r[2], const void* p) {
    unsigned int a = (unsigned int)__cvta_generic_to_shared(p);
    asm volatile("ldmatrix.sync.aligned.m8n8.x2.shared.b16 {%0,%1}, [%2];"
        : "=r"(r[0]), "=r"(r[1]) : "r"(a));
}

__device__ __forceinline__ void cp16(void* smem_ptr, const void* gptr) {
    unsigned int sa = (unsigned int)__cvta_generic_to_shared(smem_ptr);
    asm volatile("cp.async.cg.shared.global [%0], [%1], 16;\n" :: "r"(sa), "l"(gptr));
}
#define CP_COMMIT() asm volatile("cp.async.commit_group;\n")
#define CP_WAIT1()  asm volatile("cp.async.wait_group 1;\n")
#define CP_WAIT0()  asm volatile("cp.async.wait_group 0;\n")

#define C1SC 0.18033688f   // 0.125 * log2(e)

// ---------------- fp32 -> half elementwise ------------------------------------------
__global__ void cvt_h_kernel(const float4* __restrict__ src, uint2* __restrict__ dst, int n4) {
    int i = blockIdx.x*256 + threadIdx.x;
    if (i < n4) {
        float4 v = src[i];
        uint2 o;
        o.x = pk2(v.x, v.y);
        o.y = pk2(v.z, v.w);
        dst[i] = o;
    }
}

// ---------------- transpose + cvt: WT[n][k] = half(W[k][n]) -------------------------
__global__ void transpose_h_kernel(const float* __restrict__ W, __half* __restrict__ WT,
                                   int K, int N) {
    __shared__ float tile[32][33];
    int k0 = blockIdx.x*32, n0 = blockIdx.y*32;
    int tx = threadIdx.x, ty = threadIdx.y;
    #pragma unroll
    for (int i = ty; i < 32; i += 8)
        tile[i][tx] = W[(size_t)(k0+i)*N + n0 + tx];
    __syncthreads();
    #pragma unroll
    for (int i = ty; i < 32; i += 8)
        WT[(size_t)(n0+i)*K + k0 + tx] = __float2half_rn(tile[tx][i]);
}

// ---------------- fp16 tensor-core GEMM: C[M,N] = A[M,K] * Bt[N,K]^T ---------------
// Block 128x128x64, 128 threads = 4 warps (2x2), warp tile 64x64.
// 3-stage cp.async pipeline, ldmatrix fragment loads.
// HOUT==1: qkv output — q/k columns to g_qkvh (half), v columns (>=2C) transposed
//          into g_vt. HOUT==0: fp32 output (final proj).
#define GRS 72                 // row stride in halves (144B)
#define GTILEH (128*GRS)       // halves per (A or B) tile

template<int HOUT>
__global__ __launch_bounds__(128, 2) void gemm_f16(
        const __half* __restrict__ A, const __half* __restrict__ Bt,
        void* __restrict__ Cout, int M, int N, int K) {
    extern __shared__ __half gsh[];   // [3][2][GTILEH]

    int tid = threadIdx.x;
    int lane = tid & 31, warp = tid >> 5;
    int wm = warp >> 1, wn = warp & 1;
    int g = lane >> 2, t = lane & 3;
    int m0 = blockIdx.y*128, n0 = blockIdx.x*128;
    int nkt = K / 64;

    const int a_lr = wm*64 + (lane & 15);
    const int a_lc = (lane >> 4) * 8;
    const int b_lr = wn*64 + (lane & 7);
    const int b_lc = ((lane >> 3) & 1) * 8;

    float acc[4][8][4];
    #pragma unroll
    for (int i = 0; i < 4; i++)
        #pragma unroll
        for (int j = 0; j < 8; j++)
            #pragma unroll
            for (int r = 0; r < 4; r++) acc[i][j][r] = 0.f;

    auto stage = [&](int kt, int s) {
        __half* Ad = gsh + s*2*GTILEH;
        __half* Bd = Ad + GTILEH;
        #pragma unroll
        for (int i = 0; i < 8; i++) {
            int idx = tid + i*128;          // 0..1023
            int r = idx >> 3, c8 = (idx & 7)*8;
            cp16(Ad + r*GRS + c8, A + (size_t)(m0+r)*K + kt*64 + c8);
            cp16(Bd + r*GRS + c8, Bt + (size_t)(n0+r)*K + kt*64 + c8);
        }
    };

    stage(0, 0); CP_COMMIT();
    stage(1, 1); CP_COMMIT();

    for (int kt = 0; kt < nkt; kt++) {
        CP_WAIT1();
        __syncthreads();
        if (kt + 2 < nkt) stage(kt+2, (kt+2)%3);
        CP_COMMIT();

        const __half* Ab = gsh + (kt%3)*2*GTILEH;
        const __half* Bb = Ab + GTILEH;

        #pragma unroll
        for (int ks = 0; ks < 4; ks++) {
            int k = ks*16;
            unsigned int af[4][4];
            #pragma unroll
            for (int mt = 0; mt < 4; mt++)
                ldsm_x4(af[mt], &Ab[(a_lr + mt*16)*GRS + k + a_lc]);
            unsigned int bf[8][2];
            #pragma unroll
            for (int nt = 0; nt < 8; nt++)
                ldsm_x2(bf[nt], &Bb[(b_lr + nt*8)*GRS + k + b_lc]);
            #pragma unroll
            for (int mt = 0; mt < 4; mt++)
                #pragma unroll
                for (int nt = 0; nt < 8; nt++)
                    mma_f16(acc[mt][nt], af[mt], bf[nt]);
        }
    }

    #pragma unroll
    for (int mt = 0; mt < 4; mt++) {
        int r = m0 + wm*64 + mt*16 + g;
        #pragma unroll
        for (int nt = 0; nt < 8; nt++) {
            int c = n0 + wn*64 + nt*8 + 2*t;
            if (HOUT) {
                if (c >= 2*CC) {
                    // v region: write transposed into g_vt[(b,h,d)][t]
                    int d = c - 2*CC;
                    int hh = d >> 6, dl = d & 63;
                    int bb = r / TT, tp = r % TT;
                    __half* vdst = g_vt + ((size_t)(bb*HH + hh)*HS + dl)*TT + tp;
                    vdst[0]      = __float2half_rn(acc[mt][nt][0]);
                    vdst[TT]     = __float2half_rn(acc[mt][nt][1]);
                    vdst[8]      = __float2half_rn(acc[mt][nt][2]);
                    vdst[TT + 8] = __float2half_rn(acc[mt][nt][3]);
                } else {
                    __half* Ch = (__half*)Cout;
                    *(unsigned int*)&Ch[(size_t)r*N + c]     = pk2(acc[mt][nt][0], acc[mt][nt][1]);
                    *(unsigned int*)&Ch[(size_t)(r+8)*N + c] = pk2(acc[mt][nt][2], acc[mt][nt][3]);
                }
            } else {
                float* Cf = (float*)Cout;
                *(float2*)&Cf[(size_t)r*N + c]     = make_float2(acc[mt][nt][0], acc[mt][nt][1]);
                *(float2*)&Cf[(size_t)(r+8)*N + c] = make_float2(acc[mt][nt][2], acc[mt][nt][3]);
            }
        }
    }
}

// ---------------- fp16 mma attention: grid (T/128, H, B), block 256 (8 warps) ------
// Two-pass flash, fp16 operands, fp32 softmax, ldmatrix fragment loads.
#define KST 72   // halves per row (144B)
#define VST 72

__device__ __forceinline__ void stageK(__half* dst, const __half* src, int tid) {
    #pragma unroll
    for (int i = tid; i < 512; i += 256) {
        int r = i >> 3, c8 = (i & 7)*8;
        cp16(dst + r*KST + c8, src + (size_t)r*C3 + c8);
    }
}

__device__ __forceinline__ void stageV(__half* dst, const __half* src, int tid) {
    #pragma unroll
    for (int i = tid; i < 512; i += 256) {
        int r = i >> 3, c8 = (i & 7)*8;
        cp16(dst + r*VST + c8, src + (size_t)r*TT + c8);
    }
}

__global__ __launch_bounds__(256, 2) void attn_mma(const int* __restrict__ amask) {
    extern __shared__ __half smh[];
    __half* Ks = smh;                      // [2][64*KST]
    __half* Vs = smh + 2*64*KST;           // [2][64*VST]
    __half* Ps = Vs + 2*64*VST;            // [128*KST] (Q staging, then P)
    float* kvl = (float*)(Ps + 128*KST);   // [2][64] additive key mask

    const int tid = threadIdx.x;
    const int lane = tid & 31, warp = tid >> 5;
    const int g = lane >> 2, t = lane & 3;
    const int qt = (TT/128 - 1) - blockIdx.x;
    const int h = blockIdx.y, b = blockIdx.z;
    const int qbase = qt*128;
    const int nkt = 2*qt + 2;

    const __half* qsrc = g_qkvh + (size_t)(b*TT+qbase)*C3 + h*HS;
    const __half* kall = g_qkvh + (size_t)(b*TT)*C3 + CC + h*HS;
    const __half* vtall = g_vt + (size_t)(b*HH + h)*HS*TT;

    const int wrow0 = qbase + warp*16;
    const int gr0 = wrow0 + g;
    const int gr1 = gr0 + 8;

    const int x4_lr = lane & 15;
    const int x4_lc = (lane >> 4) * 8;
    const int x2_lr = lane & 7;
    const int x2_lc = ((lane >> 3) & 1) * 8;

    // ---- prologue: stage Q (128 rows) -> Ps and K0 -> Ks[0] ----
    #pragma unroll
    for (int i = tid; i < 1024; i += 256) {
        int r = i >> 3, c8 = (i & 7)*8;
        cp16(Ps + r*KST + c8, qsrc + (size_t)r*C3 + c8);
    }
    stageK(Ks, kall, tid);
    if (tid < 64) kvl[tid] = amask[b*TT + tid] ? 0.f : -1e30f;
    CP_COMMIT();
    CP_WAIT0();
    __syncthreads();

    unsigned int qa[4][4];
    #pragma unroll
    for (int c = 0; c < 4; c++)
        ldsm_x4(qa[c], &Ps[(warp*16 + x4_lr)*KST + 16*c + x4_lc]);

    float l0 = 0.f, l1 = 0.f;

    // ================= Pass A: row sums =================
    for (int kt = 0; kt < nkt; kt++) {
        const int kbase = kt*64;
        CP_WAIT0();
        __syncthreads();
        if (kt + 1 < nkt) {
            stageK(Ks + ((kt+1)&1)*64*KST, kall + (size_t)(kbase+64)*C3, tid);
            if (tid < 64) kvl[((kt+1)&1)*64 + tid] = amask[b*TT + kbase+64 + tid] ? 0.f : -1e30f;
        }
        CP_COMMIT();

        const __half* K0 = Ks + (kt&1)*64*KST;
        const float* kv = kvl + (kt&1)*64;

        float s[8][4];
        #pragma unroll
        for (int j = 0; j < 8; j++) { s[j][0]=s[j][1]=s[j][2]=s[j][3]=0.f; }
        #pragma unroll
        for (int c = 0; c < 4; c++) {
            #pragma unroll
            for (int j = 0; j < 8; j++) {
                unsigned int bf[2];
                ldsm_x2(bf, &K0[(8*j + x2_lr)*KST + 16*c + x2_lc]);
                mma_f16(s[j], qa[c], bf);
            }
        }
        float ts0 = 0.f, ts1 = 0.f;
        if (kbase + 63 <= wrow0) {   // interior
            #pragma unroll
            for (int j = 0; j < 8; j++) {
                float kv0 = kv[8*j+2*t], kv1 = kv[8*j+2*t+1];
                ts0 += ex2f(fmaf(s[j][0], C1SC, kv0)) + ex2f(fmaf(s[j][1], C1SC, kv1));
                ts1 += ex2f(fmaf(s[j][2], C1SC, kv0)) + ex2f(fmaf(s[j][3], C1SC, kv1));
            }
        } else {                     // diagonal
            #pragma unroll
            for (int j = 0; j < 8; j++) {
                int c0 = kbase + 8*j + 2*t;
                float kv0 = kv[8*j+2*t], kv1 = kv[8*j+2*t+1];
                float v0 = fmaf(s[j][0], C1SC, kv0); if (c0   > gr0) v0 = -1e30f;
                float v1 = fmaf(s[j][1], C1SC, kv1); if (c0+1 > gr0) v1 = -1e30f;
                float v2 = fmaf(s[j][2], C1SC, kv0); if (c0   > gr1) v2 = -1e30f;
                float v3 = fmaf(s[j][3], C1SC, kv1); if (c0+1 > gr1) v3 = -1e30f;
                ts0 += ex2f(v0) + ex2f(v1);
                ts1 += ex2f(v2) + ex2f(v3);
            }
        }
        ts0 += __shfl_xor_sync(0xffffffffu, ts0, 1);
        ts0 += __shfl_xor_sync(0xffffffffu, ts0, 2);
        ts1 += __shfl_xor_sync(0xffffffffu, ts1, 1);
        ts1 += __shfl_xor_sync(0xffffffffu, ts1, 2);
        l0 += ts0;
        l1 += ts1;
    }
    const float li0 = 1.0f/l0, li1 = 1.0f/l1;

    // ================= Pass B: output + importance =================
    float o[8][4];
    #pragma unroll
    for (int j = 0; j < 8; j++) { o[j][0]=o[j][1]=o[j][2]=o[j][3]=0.f; }

    __syncthreads();
    stageK(Ks, kall, tid);
    stageV(Vs, vtall, tid);
    if (tid < 64) kvl[tid] = amask[b*TT + tid] ? 0.f : -1e30f;
    CP_COMMIT();

    for (int kt = 0; kt < nkt; kt++) {
        const int kbase = kt*64;
        CP_WAIT0();
        __syncthreads();
        if (kt + 1 < nkt) {
            stageK(Ks + ((kt+1)&1)*64*KST, kall + (size_t)(kbase+64)*C3, tid);
            stageV(Vs + ((kt+1)&1)*64*VST, vtall + kbase + 64, tid);
            if (tid < 64) kvl[((kt+1)&1)*64 + tid] = amask[b*TT + kbase+64 + tid] ? 0.f : -1e30f;
        }
        CP_COMMIT();

        const __half* K0 = Ks + (kt&1)*64*KST;
        const __half* V0 = Vs + (kt&1)*64*VST;
        const float* kv = kvl + (kt&1)*64;

        float s[8][4];
        #pragma unroll
        for (int j = 0; j < 8; j++) { s[j][0]=s[j][1]=s[j][2]=s[j][3]=0.f; }
        #pragma unroll
        for (int c = 0; c < 4; c++) {
            #pragma unroll
            for (int j = 0; j < 8; j++) {
                unsigned int bf[2];
                ldsm_x2(bf, &K0[(8*j + x2_lr)*KST + 16*c + x2_lc]);
                mma_f16(s[j], qa[c], bf);
            }
        }
        const bool interior = (kbase + 63 <= wrow0);
        float* imp_base = &g_imp[b*TT + kbase];
        #pragma unroll
        for (int j = 0; j < 8; j++) {
            int c0 = kbase + 8*j + 2*t;
            float kv0 = kv[8*j+2*t], kv1 = kv[8*j+2*t+1];
            float v0 = fmaf(s[j][0], C1SC, kv0);
            float v1 = fmaf(s[j][1], C1SC, kv1);
            float v2 = fmaf(s[j][2], C1SC, kv0);
            float v3 = fmaf(s[j][3], C1SC, kv1);
            if (!interior) {
                if (c0   > gr0) v0 = -1e30f;
                if (c0+1 > gr0) v1 = -1e30f;
                if (c0   > gr1) v2 = -1e30f;
                if (c0+1 > gr1) v3 = -1e30f;
            }
            float p0 = ex2f(v0) * li0;
            float p1 = ex2f(v1) * li0;
            float p2 = ex2f(v2) * li1;
            float p3 = ex2f(v3) * li1;
            *(unsigned int*)&Ps[(warp*16+g)*KST   + 8*j + 2*t] = pk2(p0, p1);
            *(unsigned int*)&Ps[(warp*16+g+8)*KST + 8*j + 2*t] = pk2(p2, p3);
            float cA = p0 + p2;
            float cB = p1 + p3;
            cA += __shfl_xor_sync(0xffffffffu, cA, 4);
            cA += __shfl_xor_sync(0xffffffffu, cA, 8);
            cA += __shfl_xor_sync(0xffffffffu, cA, 16);
            cB += __shfl_xor_sync(0xffffffffu, cB, 4);
            cB += __shfl_xor_sync(0xffffffffu, cB, 8);
            cB += __shfl_xor_sync(0xffffffffu, cB, 16);
            if (g == 0) {
                atomicAdd(imp_base + 8*j + 2*t,     cA);
                atomicAdd(imp_base + 8*j + 2*t + 1, cB);
            }
        }
        // O += P @ V (Vt layout: rows d, cols key)
        #pragma unroll
        for (int c = 0; c < 4; c++) {
            unsigned int pa[4];
            ldsm_x4(pa, &Ps[(warp*16 + x4_lr)*KST + 16*c + x4_lc]);
            #pragma unroll
            for (int j = 0; j < 8; j++) {
                unsigned int bv[2];
                ldsm_x2(bv, &V0[(8*j + x2_lr)*VST + 16*c + x2_lc]);
                mma_f16(o[j], pa, bv);
            }
        }
    }

    // write O to g_atty (half)
    __half* ydst = g_atty + (size_t)(b*TT)*CC + h*HS;
    #pragma unroll
    for (int j = 0; j < 8; j++) {
        int col = 8*j + 2*t;
        *(unsigned int*)&ydst[(size_t)gr0*CC + col] = pk2(o[j][0], o[j][1]);
        *(unsigned int*)&ydst[(size_t)gr1*CC + col] = pk2(o[j][2], o[j][3]);
    }
}

__global__ void zero_imp_kernel() {
    int i = blockIdx.x*256 + threadIdx.x;
    if (i < BB*TT) g_imp[i] = 0.f;
}

__global__ void finalize_imp_kernel(float* __restrict__ out) {
    int i = blockIdx.x*256 + threadIdx.x;
    if (i < BB*TT) out[i] = g_imp[i] * (1.0f / (HH * (float)TT));
}

extern "C" void kernel_launch(void* const* d_in, const int* in_sizes, int n_in,
                              void* d_out, int out_size) {
    const float* x      = (const float*)d_in[0];
    const int*   amask  = (const int*)d_in[1];
    const float* w_attn = (const float*)d_in[2];
    const float* w_proj = (const float*)d_in[3];
    float* out = (float*)d_out;

    __half *qkvhp, *attyp, *xhp, *wahp, *wphp;
    cudaGetSymbolAddress((void**)&qkvhp, g_qkvh);
    cudaGetSymbolAddress((void**)&attyp, g_atty);
    cudaGetSymbolAddress((void**)&xhp, g_xh);
    cudaGetSymbolAddress((void**)&wahp, g_wah);
    cudaGetSymbolAddress((void**)&wphp, g_wph);

    const int ASMEM = (2*64*KST + 2*64*VST + 128*KST)*2 + 2*64*4;  // 55,808 B
    cudaFuncSetAttribute(attn_mma, cudaFuncAttributeMaxDynamicSharedMemorySize, ASMEM);
    const int GSMEM = 3*2*GTILEH*2;  // 110,592 B
    cudaFuncSetAttribute(gemm_f16<1>, cudaFuncAttributeMaxDynamicSharedMemorySize, GSMEM);
    cudaFuncSetAttribute(gemm_f16<0>, cudaFuncAttributeMaxDynamicSharedMemorySize, GSMEM);

    // 0) convert x to half; transpose+convert weights
    cvt_h_kernel<<<(BB*TT*CC/4 + 255)/256, 256>>>((const float4*)x, (uint2*)xhp, BB*TT*CC/4);
    transpose_h_kernel<<<dim3(CC/32, C3/32), dim3(32,8)>>>(w_attn, wahp, CC, C3);
    transpose_h_kernel<<<dim3(CC/32, CC/32), dim3(32,8)>>>(w_proj, wphp, CC, CC);
    // 1) qkv = x @ w_attn; v columns written transposed into g_vt directly
    gemm_f16<1><<<dim3(C3/128, (BB*TT)/128), 128, GSMEM>>>(xhp, wahp, qkvhp, BB*TT, C3, CC);
    // 2) zero importance accumulator
    zero_imp_kernel<<<(BB*TT + 255)/256, 256>>>();
    // 3) attention + importance (fp16 mma + ldmatrix)
    attn_mma<<<dim3(TT/128, HH, BB), 256, ASMEM>>>(amask);
    // 4) importance -> d_out tail
    finalize_imp_kernel<<<(BB*TT + 255)/256, 256>>>(out + (size_t)BB*TT*CC);
    // 5) y = atty @ w_proj -> d_out head (fp32 out)
    gemm_f16<0><<<dim3(CC/128, (BB*TT)/128), 128, GSMEM>>>(attyp, wphp, out, BB*TT, CC, CC);
}

// round 16
// speedup vs baseline: 2.1540x; 1.2316x over previous
#include <cuda_runtime.h>
#include <cuda_fp16.h>
#include <stdint.h>
#include <math.h>

#define BB 4
#define TT 2048
#define CC 768
#define HH 12
#define HS 64
#define C3 (3*CC)
#define NQT (TT/128)

// ---------------- scratch (static device globals; no allocations) ----------------
__device__ __half g_qkvh[(size_t)BB*TT*C3];    // (B,T,3C) half
__device__ __half g_atty[(size_t)BB*TT*CC];    // attention out, half
__device__ __half g_xh[(size_t)BB*TT*CC];      // x as half
__device__ __half g_wah[(size_t)C3*CC];        // w_attn^T [3C][C] half
__device__ __half g_wph[(size_t)CC*CC];        // w_proj^T [C][C] half
__device__ float  g_imp[BB*TT + 1];            // importance accumulator (+1 pad slot)
__device__ int    g_cidx[BB][TT + 64];         // compacted valid-key indices (padded)
__device__ int    g_cnt[BB*NQT];               // valid keys with orig < (qt+1)*128

// ---------------- helpers ----------------------------------------------------------
__device__ __forceinline__ float ex2f(float x) {
    float r;
    asm("ex2.approx.f32 %0, %1;" : "=f"(r) : "f"(x));
    return r;
}

__device__ __forceinline__ unsigned int pk2(float a, float b) {
    __half2 h = __floats2half2_rn(a, b);
    return *(unsigned int*)&h;
}

__device__ __forceinline__ void mma_f16(float c[4], const unsigned int a[4], const unsigned int b[2]) {
    asm volatile(
        "mma.sync.aligned.m16n8k16.row.col.f32.f16.f16.f32 "
        "{%0,%1,%2,%3}, {%4,%5,%6,%7}, {%8,%9}, {%0,%1,%2,%3};"
        : "+f"(c[0]), "+f"(c[1]), "+f"(c[2]), "+f"(c[3])
        : "r"(a[0]), "r"(a[1]), "r"(a[2]), "r"(a[3]), "r"(b[0]), "r"(b[1]));
}

__device__ __forceinline__ void ldsm_x4(unsigned int r[4], const void* p) {
    unsigned int a = (unsigned int)__cvta_generic_to_shared(p);
    asm volatile("ldmatrix.sync.aligned.m8n8.x4.shared.b16 {%0,%1,%2,%3}, [%4];"
        : "=r"(r[0]), "=r"(r[1]), "=r"(r[2]), "=r"(r[3]) : "r"(a));
}

__device__ __forceinline__ void ldsm_x2(unsigned int r[2], const void* p) {
    unsigned int a = (unsigned int)__cvta_generic_to_shared(p);
    asm volatile("ldmatrix.sync.aligned.m8n8.x2.shared.b16 {%0,%1}, [%2];"
        : "=r"(r[0]), "=r"(r[1]) : "r"(a));
}

__device__ __forceinline__ void ldsm_x2_t(unsigned int r[2], const void* p) {
    unsigned int a = (unsigned int)__cvta_generic_to_shared(p);
    asm volatile("ldmatrix.sync.aligned.m8n8.x2.trans.shared.b16 {%0,%1}, [%2];"
        : "=r"(r[0]), "=r"(r[1]) : "r"(a));
}

__device__ __forceinline__ void cp16(void* smem_ptr, const void* gptr) {
    unsigned int sa = (unsigned int)__cvta_generic_to_shared(smem_ptr);
    asm volatile("cp.async.cg.shared.global [%0], [%1], 16;\n" :: "r"(sa), "l"(gptr));
}
#define CP_COMMIT() asm volatile("cp.async.commit_group;\n")
#define CP_WAIT1()  asm volatile("cp.async.wait_group 1;\n")
#define CP_WAIT0()  asm volatile("cp.async.wait_group 0;\n")

#define C1SC 0.18033688f   // 0.125 * log2(e)

// ---------------- fp32 -> half elementwise ------------------------------------------
__global__ void cvt_h_kernel(const float4* __restrict__ src, uint2* __restrict__ dst, int n4) {
    int i = blockIdx.x*256 + threadIdx.x;
    if (i < n4) {
        float4 v = src[i];
        uint2 o;
        o.x = pk2(v.x, v.y);
        o.y = pk2(v.z, v.w);
        dst[i] = o;
    }
}

// ---------------- transpose + cvt: WT[n][k] = half(W[k][n]) -------------------------
__global__ void transpose_h_kernel(const float* __restrict__ W, __half* __restrict__ WT,
                                   int K, int N) {
    __shared__ float tile[32][33];
    int k0 = blockIdx.x*32, n0 = blockIdx.y*32;
    int tx = threadIdx.x, ty = threadIdx.y;
    #pragma unroll
    for (int i = ty; i < 32; i += 8)
        tile[i][tx] = W[(size_t)(k0+i)*N + n0 + tx];
    __syncthreads();
    #pragma unroll
    for (int i = ty; i < 32; i += 8)
        WT[(size_t)(n0+i)*K + k0 + tx] = __float2half_rn(tile[tx][i]);
}

// ---------------- mask compaction: per-b prefix scan --------------------------------
__global__ void compact_kernel(const int* __restrict__ amask) {   // grid BB, block 256
    __shared__ int part[256];
    int b = blockIdx.x, tid = threadIdx.x;
    int loc[8]; int cnt = 0;
    #pragma unroll
    for (int i = 0; i < 8; i++) {
        loc[i] = amask[b*TT + tid*8 + i] != 0;
        cnt += loc[i];
    }
    part[tid] = cnt;
    __syncthreads();
    // inclusive scan over 256 thread partials
    for (int off = 1; off < 256; off <<= 1) {
        int v = (tid >= off) ? part[tid - off] : 0;
        __syncthreads();
        part[tid] += v;
        __syncthreads();
    }
    int pos = part[tid] - cnt;   // exclusive prefix
    #pragma unroll
    for (int i = 0; i < 8; i++) {
        if (loc[i]) g_cidx[b][pos++] = tid*8 + i;
    }
    if (tid < NQT) g_cnt[b*NQT + tid] = part[(tid+1)*16 - 1];
    int total = part[255];
    int padded = (total + 63) & ~63;
    for (int i = total + tid; i < padded; i += 256) g_cidx[b][i] = TT;
}

// ---------------- fp16 tensor-core GEMM: C[M,N] = A[M,K] * Bt[N,K]^T ---------------
// Block 128x128x64, 128 threads = 4 warps (2x2), warp tile 64x64, ldmatrix loads.
#define GRS 72
#define GTILEH (128*GRS)

template<int HOUT>
__global__ __launch_bounds__(128, 2) void gemm_f16(
        const __half* __restrict__ A, const __half* __restrict__ Bt,
        void* __restrict__ Cout, int M, int N, int K) {
    extern __shared__ __half gsh[];   // [3][2][GTILEH]

    int tid = threadIdx.x;
    int lane = tid & 31, warp = tid >> 5;
    int wm = warp >> 1, wn = warp & 1;
    int g = lane >> 2, t = lane & 3;
    int m0 = blockIdx.y*128, n0 = blockIdx.x*128;
    int nkt = K / 64;

    const int a_lr = wm*64 + (lane & 15);
    const int a_lc = (lane >> 4) * 8;
    const int b_lr = wn*64 + (lane & 7);
    const int b_lc = ((lane >> 3) & 1) * 8;

    float acc[4][8][4];
    #pragma unroll
    for (int i = 0; i < 4; i++)
        #pragma unroll
        for (int j = 0; j < 8; j++)
            #pragma unroll
            for (int r = 0; r < 4; r++) acc[i][j][r] = 0.f;

    auto stage = [&](int kt, int s) {
        __half* Ad = gsh + s*2*GTILEH;
        __half* Bd = Ad + GTILEH;
        #pragma unroll
        for (int i = 0; i < 8; i++) {
            int idx = tid + i*128;
            int r = idx >> 3, c8 = (idx & 7)*8;
            cp16(Ad + r*GRS + c8, A + (size_t)(m0+r)*K + kt*64 + c8);
            cp16(Bd + r*GRS + c8, Bt + (size_t)(n0+r)*K + kt*64 + c8);
        }
    };

    stage(0, 0); CP_COMMIT();
    stage(1, 1); CP_COMMIT();

    for (int kt = 0; kt < nkt; kt++) {
        CP_WAIT1();
        __syncthreads();
        if (kt + 2 < nkt) stage(kt+2, (kt+2)%3);
        CP_COMMIT();

        const __half* Ab = gsh + (kt%3)*2*GTILEH;
        const __half* Bb = Ab + GTILEH;

        #pragma unroll
        for (int ks = 0; ks < 4; ks++) {
            int k = ks*16;
            unsigned int af[4][4];
            #pragma unroll
            for (int mt = 0; mt < 4; mt++)
                ldsm_x4(af[mt], &Ab[(a_lr + mt*16)*GRS + k + a_lc]);
            unsigned int bf[8][2];
            #pragma unroll
            for (int nt = 0; nt < 8; nt++)
                ldsm_x2(bf[nt], &Bb[(b_lr + nt*8)*GRS + k + b_lc]);
            #pragma unroll
            for (int mt = 0; mt < 4; mt++)
                #pragma unroll
                for (int nt = 0; nt < 8; nt++)
                    mma_f16(acc[mt][nt], af[mt], bf[nt]);
        }
    }

    #pragma unroll
    for (int mt = 0; mt < 4; mt++) {
        int r = m0 + wm*64 + mt*16 + g;
        #pragma unroll
        for (int nt = 0; nt < 8; nt++) {
            int c = n0 + wn*64 + nt*8 + 2*t;
            if (HOUT) {
                __half* Ch = (__half*)Cout;
                *(unsigned int*)&Ch[(size_t)r*N + c]     = pk2(acc[mt][nt][0], acc[mt][nt][1]);
                *(unsigned int*)&Ch[(size_t)(r+8)*N + c] = pk2(acc[mt][nt][2], acc[mt][nt][3]);
            } else {
                float* Cf = (float*)Cout;
                *(float2*)&Cf[(size_t)r*N + c]     = make_float2(acc[mt][nt][0], acc[mt][nt][1]);
                *(float2*)&Cf[(size_t)(r+8)*N + c] = make_float2(acc[mt][nt][2], acc[mt][nt][3]);
            }
        }
    }
}

// ---------------- fp16 mma attention with key compaction ----------------------------
// grid (T/128, H, B), block 256 (8 warps). Two-pass flash over COMPACTED key tiles.
#define KST 72
#define VST 72

// gather-stage 64 rows (K or V, row-major [key][d]) via compacted indices
__device__ __forceinline__ void stageG(__half* dst, const __half* src,
                                       const int* __restrict__ cidx, int kbase, int tid) {
    #pragma unroll
    for (int i = tid; i < 512; i += 256) {
        int r = i >> 3, c8 = (i & 7)*8;
        int orig = cidx[kbase + r];
        if (orig > TT-1) orig = TT-1;   // pad clamp (data unused, masked)
        cp16(dst + r*KST + c8, src + (size_t)orig*C3 + c8);
    }
}

__global__ __launch_bounds__(256, 2) void attn_mma(const int* __restrict__ amask) {
    extern __shared__ __half smh[];
    __half* Ks = smh;                      // [2][64*KST]
    __half* Vs = smh + 2*64*KST;           // [2][64*VST]
    __half* Ps = Vs + 2*64*VST;            // [128*KST] (Q staging, then P)
    int* ci    = (int*)(Ps + 128*KST);     // [2][64] compacted orig indices

    const int tid = threadIdx.x;
    const int lane = tid & 31, warp = tid >> 5;
    const int g = lane >> 2, t = lane & 3;
    const int qt = (NQT - 1) - blockIdx.x;
    const int h = blockIdx.y, b = blockIdx.z;
    const int qbase = qt*128;

    const int cnt = g_cnt[b*NQT + qt];       // valid keys with orig < qbase+128
    const int nkt = (cnt + 63) >> 6;
    const int* cidx = g_cidx[b];

    const __half* qsrc = g_qkvh + (size_t)(b*TT+qbase)*C3 + h*HS;
    const __half* kall = g_qkvh + (size_t)(b*TT)*C3 + CC + h*HS;
    const __half* vall = g_qkvh + (size_t)(b*TT)*C3 + 2*CC + h*HS;

    const int wrow0 = qbase + warp*16;
    const int gr0 = wrow0 + g;
    const int gr1 = gr0 + 8;

    const int x4_lr = lane & 15;
    const int x4_lc = (lane >> 4) * 8;
    const int x2_lr = lane & 7;
    const int x2_lc = ((lane >> 3) & 1) * 8;

    // ---- prologue: stage Q (128 rows) -> Ps and K tile 0 ----
    #pragma unroll
    for (int i = tid; i < 1024; i += 256) {
        int r = i >> 3, c8 = (i & 7)*8;
        cp16(Ps + r*KST + c8, qsrc + (size_t)r*C3 + c8);
    }
    stageG(Ks, kall, cidx, 0, tid);
    if (tid < 64) ci[tid] = cidx[tid];
    CP_COMMIT();
    CP_WAIT0();
    __syncthreads();

    unsigned int qa[4][4];
    #pragma unroll
    for (int c = 0; c < 4; c++)
        ldsm_x4(qa[c], &Ps[(warp*16 + x4_lr)*KST + 16*c + x4_lc]);

    float l0 = 0.f, l1 = 0.f;

    // ================= Pass A: row sums =================
    for (int kt = 0; kt < nkt; kt++) {
        const int kbase = kt*64;
        CP_WAIT0();
        __syncthreads();
        if (kt + 1 < nkt) {
            stageG(Ks + ((kt+1)&1)*64*KST, kall, cidx, kbase+64, tid);
            if (tid < 64) ci[((kt+1)&1)*64 + tid] = cidx[kbase+64 + tid];
        }
        CP_COMMIT();

        const __half* K0 = Ks + (kt&1)*64*KST;
        const int* cit = ci + (kt&1)*64;

        float s[8][4];
        #pragma unroll
        for (int j = 0; j < 8; j++) { s[j][0]=s[j][1]=s[j][2]=s[j][3]=0.f; }
        #pragma unroll
        for (int c = 0; c < 4; c++) {
            #pragma unroll
            for (int j = 0; j < 8; j++) {
                unsigned int bf[2];
                ldsm_x2(bf, &K0[(8*j + x2_lr)*KST + 16*c + x2_lc]);
                mma_f16(s[j], qa[c], bf);
            }
        }
        float ts0 = 0.f, ts1 = 0.f;
        if (cit[63] <= wrow0) {      // interior: all keys causally visible, all valid
            #pragma unroll
            for (int j = 0; j < 8; j++) {
                ts0 += ex2f(s[j][0]*C1SC) + ex2f(s[j][1]*C1SC);
                ts1 += ex2f(s[j][2]*C1SC) + ex2f(s[j][3]*C1SC);
            }
        } else {                     // diagonal/tail: causal check on orig indices
            #pragma unroll
            for (int j = 0; j < 8; j++) {
                int c0 = cit[8*j+2*t], c1 = cit[8*j+2*t+1];
                float v0 = s[j][0]*C1SC; if (c0 > gr0) v0 = -1e30f;
                float v1 = s[j][1]*C1SC; if (c1 > gr0) v1 = -1e30f;
                float v2 = s[j][2]*C1SC; if (c0 > gr1) v2 = -1e30f;
                float v3 = s[j][3]*C1SC; if (c1 > gr1) v3 = -1e30f;
                ts0 += ex2f(v0) + ex2f(v1);
                ts1 += ex2f(v2) + ex2f(v3);
            }
        }
        ts0 += __shfl_xor_sync(0xffffffffu, ts0, 1);
        ts0 += __shfl_xor_sync(0xffffffffu, ts0, 2);
        ts1 += __shfl_xor_sync(0xffffffffu, ts1, 1);
        ts1 += __shfl_xor_sync(0xffffffffu, ts1, 2);
        l0 += ts0;
        l1 += ts1;
    }
    const float li0 = 1.0f/l0, li1 = 1.0f/l1;

    // ================= Pass B: output + importance =================
    float o[8][4];
    #pragma unroll
    for (int j = 0; j < 8; j++) { o[j][0]=o[j][1]=o[j][2]=o[j][3]=0.f; }

    __syncthreads();
    stageG(Ks, kall, cidx, 0, tid);
    stageG(Vs, vall, cidx, 0, tid);
    if (tid < 64) ci[tid] = cidx[tid];
    CP_COMMIT();

    for (int kt = 0; kt < nkt; kt++) {
        const int kbase = kt*64;
        CP_WAIT0();
        __syncthreads();
        if (kt + 1 < nkt) {
            stageG(Ks + ((kt+1)&1)*64*KST, kall, cidx, kbase+64, tid);
            stageG(Vs + ((kt+1)&1)*64*VST, vall, cidx, kbase+64, tid);
            if (tid < 64) ci[((kt+1)&1)*64 + tid] = cidx[kbase+64 + tid];
        }
        CP_COMMIT();

        const __half* K0 = Ks + (kt&1)*64*KST;
        const __half* V0 = Vs + (kt&1)*64*VST;
        const int* cit = ci + (kt&1)*64;

        float s[8][4];
        #pragma unroll
        for (int j = 0; j < 8; j++) { s[j][0]=s[j][1]=s[j][2]=s[j][3]=0.f; }
        #pragma unroll
        for (int c = 0; c < 4; c++) {
            #pragma unroll
            for (int j = 0; j < 8; j++) {
                unsigned int bf[2];
                ldsm_x2(bf, &K0[(8*j + x2_lr)*KST + 16*c + x2_lc]);
                mma_f16(s[j], qa[c], bf);
            }
        }
        const bool interior = (cit[63] <= wrow0);
        #pragma unroll
        for (int j = 0; j < 8; j++) {
            int c0 = cit[8*j+2*t], c1 = cit[8*j+2*t+1];
            float v0 = s[j][0]*C1SC;
            float v1 = s[j][1]*C1SC;
            float v2 = s[j][2]*C1SC;
            float v3 = s[j][3]*C1SC;
            if (!interior) {
                if (c0 > gr0) v0 = -1e30f;
                if (c1 > gr0) v1 = -1e30f;
                if (c0 > gr1) v2 = -1e30f;
                if (c1 > gr1) v3 = -1e30f;
            }
            float p0 = ex2f(v0) * li0;
            float p1 = ex2f(v1) * li0;
            float p2 = ex2f(v2) * li1;
            float p3 = ex2f(v3) * li1;
            *(unsigned int*)&Ps[(warp*16+g)*KST   + 8*j + 2*t] = pk2(p0, p1);
            *(unsigned int*)&Ps[(warp*16+g+8)*KST + 8*j + 2*t] = pk2(p2, p3);
            float cA = p0 + p2;
            float cB = p1 + p3;
            cA += __shfl_xor_sync(0xffffffffu, cA, 4);
            cA += __shfl_xor_sync(0xffffffffu, cA, 8);
            cA += __shfl_xor_sync(0xffffffffu, cA, 16);
            cB += __shfl_xor_sync(0xffffffffu, cB, 4);
            cB += __shfl_xor_sync(0xffffffffu, cB, 8);
            cB += __shfl_xor_sync(0xffffffffu, cB, 16);
            if (g == 0) {
                atomicAdd(&g_imp[b*TT + c0], cA);
                atomicAdd(&g_imp[b*TT + c1], cB);
            }
        }
        // O += P @ V  (V row-major [key][d]; B-frags via ldmatrix trans)
        #pragma unroll
        for (int c = 0; c < 4; c++) {
            unsigned int pa[4];
            ldsm_x4(pa, &Ps[(warp*16 + x4_lr)*KST + 16*c + x4_lc]);
            #pragma unroll
            for (int j = 0; j < 8; j++) {
                unsigned int bv[2];
                ldsm_x2_t(bv, &V0[(16*c + (lane & 15))*VST + 8*j]);
                mma_f16(o[j], pa, bv);
            }
        }
    }

    // write O to g_atty (half)
    __half* ydst = g_atty + (size_t)(b*TT)*CC + h*HS;
    #pragma unroll
    for (int j = 0; j < 8; j++) {
        int col = 8*j + 2*t;
        *(unsigned int*)&ydst[(size_t)gr0*CC + col] = pk2(o[j][0], o[j][1]);
        *(unsigned int*)&ydst[(size_t)gr1*CC + col] = pk2(o[j][2], o[j][3]);
    }
}

__global__ void zero_imp_kernel() {
    int i = blockIdx.x*256 + threadIdx.x;
    if (i < BB*TT + 1) g_imp[i] = 0.f;
}

__global__ void finalize_imp_kernel(float* __restrict__ out) {
    int i = blockIdx.x*256 + threadIdx.x;
    if (i < BB*TT) out[i] = g_imp[i] * (1.0f / (HH * (float)TT));
}

extern "C" void kernel_launch(void* const* d_in, const int* in_sizes, int n_in,
                              void* d_out, int out_size) {
    const float* x      = (const float*)d_in[0];
    const int*   amask  = (const int*)d_in[1];
    const float* w_attn = (const float*)d_in[2];
    const float* w_proj = (const float*)d_in[3];
    float* out = (float*)d_out;

    __half *qkvhp, *attyp, *xhp, *wahp, *wphp;
    cudaGetSymbolAddress((void**)&qkvhp, g_qkvh);
    cudaGetSymbolAddress((void**)&attyp, g_atty);
    cudaGetSymbolAddress((void**)&xhp, g_xh);
    cudaGetSymbolAddress((void**)&wahp, g_wah);
    cudaGetSymbolAddress((void**)&wphp, g_wph);

    const int ASMEM = (2*64*KST + 2*64*VST + 128*KST)*2 + 2*64*4;  // 55,808 B
    cudaFuncSetAttribute(attn_mma, cudaFuncAttributeMaxDynamicSharedMemorySize, ASMEM);
    const int GSMEM = 3*2*GTILEH*2;  // 110,592 B
    cudaFuncSetAttribute(gemm_f16<1>, cudaFuncAttributeMaxDynamicSharedMemorySize, GSMEM);
    cudaFuncSetAttribute(gemm_f16<0>, cudaFuncAttributeMaxDynamicSharedMemorySize, GSMEM);

    // 0) convert x; transpose weights; compact mask
    cvt_h_kernel<<<(BB*TT*CC/4 + 255)/256, 256>>>((const float4*)x, (uint2*)xhp, BB*TT*CC/4);
    transpose_h_kernel<<<dim3(CC/32, C3/32), dim3(32,8)>>>(w_attn, wahp, CC, C3);
    transpose_h_kernel<<<dim3(CC/32, CC/32), dim3(32,8)>>>(w_proj, wphp, CC, CC);
    compact_kernel<<<BB, 256>>>(amask);
    // 1) qkv = x @ w_attn
    gemm_f16<1><<<dim3(C3/128, (BB*TT)/128), 128, GSMEM>>>(xhp, wahp, qkvhp, BB*TT, C3, CC);
    // 2) zero importance accumulator
    zero_imp_kernel<<<(BB*TT + 256)/256, 256>>>();
    // 3) attention + importance over compacted keys
    attn_mma<<<dim3(NQT, HH, BB), 256, ASMEM>>>(amask);
    // 4) importance -> d_out tail
    finalize_imp_kernel<<<(BB*TT + 255)/256, 256>>>(out + (size_t)BB*TT*CC);
    // 5) y = atty @ w_proj -> d_out head (fp32 out)
    gemm_f16<0><<<dim3(CC/128, (BB*TT)/128), 128, GSMEM>>>(attyp, wphp, out, BB*TT, CC, CC);
}

// round 17
// speedup vs baseline: 2.1932x; 1.0182x over previous
#include <cuda_runtime.h>
#include <cuda_fp16.h>
#include <stdint.h>
#include <math.h>

#define BB 4
#define TT 2048
#define CC 768
#define HH 12
#define HS 64
#define C3 (3*CC)
#define NQT (TT/128)

// ---------------- scratch (static device globals; no allocations) ----------------
__device__ __half g_qkvh[(size_t)BB*TT*C3];    // (B,T,3C) half
__device__ __half g_atty[(size_t)BB*TT*CC];    // attention out, half
__device__ __half g_xh[(size_t)BB*TT*CC];      // x as half
__device__ __half g_wah[(size_t)C3*CC];        // w_attn^T [3C][C] half
__device__ __half g_wph[(size_t)CC*CC];        // w_proj^T [C][C] half
__device__ float  g_imp[BB*TT + 1];            // importance accumulator (+1 pad slot)
__device__ int    g_cidx[BB][TT + 64];         // compacted valid-key indices (padded)
__device__ int    g_cnt[BB*NQT];               // valid keys with orig < (qt+1)*128

// ---------------- helpers ----------------------------------------------------------
__device__ __forceinline__ unsigned int pk2(float a, float b) {
    __half2 h = __floats2half2_rn(a, b);
    return *(unsigned int*)&h;
}

__device__ __forceinline__ __half2 hexp2(__half2 x) {
    __half2 r;
    asm("ex2.approx.f16x2 %0, %1;" : "=r"(*(unsigned int*)&r) : "r"(*(unsigned int*)&x));
    return r;
}

__device__ __forceinline__ void mma_f16(float c[4], const unsigned int a[4], const unsigned int b[2]) {
    asm volatile(
        "mma.sync.aligned.m16n8k16.row.col.f32.f16.f16.f32 "
        "{%0,%1,%2,%3}, {%4,%5,%6,%7}, {%8,%9}, {%0,%1,%2,%3};"
        : "+f"(c[0]), "+f"(c[1]), "+f"(c[2]), "+f"(c[3])
        : "r"(a[0]), "r"(a[1]), "r"(a[2]), "r"(a[3]), "r"(b[0]), "r"(b[1]));
}

__device__ __forceinline__ void ldsm_x4(unsigned int r[4], const void* p) {
    unsigned int a = (unsigned int)__cvta_generic_to_shared(p);
    asm volatile("ldmatrix.sync.aligned.m8n8.x4.shared.b16 {%0,%1,%2,%3}, [%4];"
        : "=r"(r[0]), "=r"(r[1]), "=r"(r[2]), "=r"(r[3]) : "r"(a));
}

__device__ __forceinline__ void ldsm_x2(unsigned int r[2], const void* p) {
    unsigned int a = (unsigned int)__cvta_generic_to_shared(p);
    asm volatile("ldmatrix.sync.aligned.m8n8.x2.shared.b16 {%0,%1}, [%2];"
        : "=r"(r[0]), "=r"(r[1]) : "r"(a));
}

__device__ __forceinline__ void ldsm_x2_t(unsigned int r[2], const void* p) {
    unsigned int a = (unsigned int)__cvta_generic_to_shared(p);
    asm volatile("ldmatrix.sync.aligned.m8n8.x2.trans.shared.b16 {%0,%1}, [%2];"
        : "=r"(r[0]), "=r"(r[1]) : "r"(a));
}

__device__ __forceinline__ void cp16(void* smem_ptr, const void* gptr) {
    unsigned int sa = (unsigned int)__cvta_generic_to_shared(smem_ptr);
    asm volatile("cp.async.cg.shared.global [%0], [%1], 16;\n" :: "r"(sa), "l"(gptr));
}
#define CP_COMMIT() asm volatile("cp.async.commit_group;\n")
#define CP_WAIT1()  asm volatile("cp.async.wait_group 1;\n")
#define CP_WAIT0()  asm volatile("cp.async.wait_group 0;\n")

#define C1SC 0.18033688f   // 0.125 * log2(e)
#define NEGBIG -60000.0f   // in-half-range mask value; ex2 -> exactly 0

// ---------------- fp32 -> half elementwise ------------------------------------------
__global__ void cvt_h_kernel(const float4* __restrict__ src, uint2* __restrict__ dst, int n4) {
    int i = blockIdx.x*256 + threadIdx.x;
    if (i < n4) {
        float4 v = src[i];
        uint2 o;
        o.x = pk2(v.x, v.y);
        o.y = pk2(v.z, v.w);
        dst[i] = o;
    }
}

// ---------------- transpose + cvt: WT[n][k] = half(W[k][n]) -------------------------
__global__ void transpose_h_kernel(const float* __restrict__ W, __half* __restrict__ WT,
                                   int K, int N) {
    __shared__ float tile[32][33];
    int k0 = blockIdx.x*32, n0 = blockIdx.y*32;
    int tx = threadIdx.x, ty = threadIdx.y;
    #pragma unroll
    for (int i = ty; i < 32; i += 8)
        tile[i][tx] = W[(size_t)(k0+i)*N + n0 + tx];
    __syncthreads();
    #pragma unroll
    for (int i = ty; i < 32; i += 8)
        WT[(size_t)(n0+i)*K + k0 + tx] = __float2half_rn(tile[tx][i]);
}

// ---------------- mask compaction: per-b prefix scan --------------------------------
__global__ void compact_kernel(const int* __restrict__ amask) {   // grid BB, block 256
    __shared__ int part[256];
    int b = blockIdx.x, tid = threadIdx.x;
    int loc[8]; int cnt = 0;
    #pragma unroll
    for (int i = 0; i < 8; i++) {
        loc[i] = amask[b*TT + tid*8 + i] != 0;
        cnt += loc[i];
    }
    part[tid] = cnt;
    __syncthreads();
    for (int off = 1; off < 256; off <<= 1) {
        int v = (tid >= off) ? part[tid - off] : 0;
        __syncthreads();
        part[tid] += v;
        __syncthreads();
    }
    int pos = part[tid] - cnt;
    #pragma unroll
    for (int i = 0; i < 8; i++) {
        if (loc[i]) g_cidx[b][pos++] = tid*8 + i;
    }
    if (tid < NQT) g_cnt[b*NQT + tid] = part[(tid+1)*16 - 1];
    int total = part[255];
    int padded = (total + 63) & ~63;
    for (int i = total + tid; i < padded; i += 256) g_cidx[b][i] = TT;
}

// ---------------- fp16 tensor-core GEMM: C[M,N] = A[M,K] * Bt[N,K]^T ---------------
#define GRS 72
#define GTILEH (128*GRS)

template<int HOUT>
__global__ __launch_bounds__(128, 2) void gemm_f16(
        const __half* __restrict__ A, const __half* __restrict__ Bt,
        void* __restrict__ Cout, int M, int N, int K) {
    extern __shared__ __half gsh[];   // [3][2][GTILEH]

    int tid = threadIdx.x;
    int lane = tid & 31, warp = tid >> 5;
    int wm = warp >> 1, wn = warp & 1;
    int g = lane >> 2, t = lane & 3;
    int m0 = blockIdx.y*128, n0 = blockIdx.x*128;
    int nkt = K / 64;

    const int a_lr = wm*64 + (lane & 15);
    const int a_lc = (lane >> 4) * 8;
    const int b_lr = wn*64 + (lane & 7);
    const int b_lc = ((lane >> 3) & 1) * 8;

    float acc[4][8][4];
    #pragma unroll
    for (int i = 0; i < 4; i++)
        #pragma unroll
        for (int j = 0; j < 8; j++)
            #pragma unroll
            for (int r = 0; r < 4; r++) acc[i][j][r] = 0.f;

    auto stage = [&](int kt, int s) {
        __half* Ad = gsh + s*2*GTILEH;
        __half* Bd = Ad + GTILEH;
        #pragma unroll
        for (int i = 0; i < 8; i++) {
            int idx = tid + i*128;
            int r = idx >> 3, c8 = (idx & 7)*8;
            cp16(Ad + r*GRS + c8, A + (size_t)(m0+r)*K + kt*64 + c8);
            cp16(Bd + r*GRS + c8, Bt + (size_t)(n0+r)*K + kt*64 + c8);
        }
    };

    stage(0, 0); CP_COMMIT();
    stage(1, 1); CP_COMMIT();

    for (int kt = 0; kt < nkt; kt++) {
        CP_WAIT1();
        __syncthreads();
        if (kt + 2 < nkt) stage(kt+2, (kt+2)%3);
        CP_COMMIT();

        const __half* Ab = gsh + (kt%3)*2*GTILEH;
        const __half* Bb = Ab + GTILEH;

        #pragma unroll
        for (int ks = 0; ks < 4; ks++) {
            int k = ks*16;
            unsigned int af[4][4];
            #pragma unroll
            for (int mt = 0; mt < 4; mt++)
                ldsm_x4(af[mt], &Ab[(a_lr + mt*16)*GRS + k + a_lc]);
            unsigned int bf[8][2];
            #pragma unroll
            for (int nt = 0; nt < 8; nt++)
                ldsm_x2(bf[nt], &Bb[(b_lr + nt*8)*GRS + k + b_lc]);
            #pragma unroll
            for (int mt = 0; mt < 4; mt++)
                #pragma unroll
                for (int nt = 0; nt < 8; nt++)
                    mma_f16(acc[mt][nt], af[mt], bf[nt]);
        }
    }

    #pragma unroll
    for (int mt = 0; mt < 4; mt++) {
        int r = m0 + wm*64 + mt*16 + g;
        #pragma unroll
        for (int nt = 0; nt < 8; nt++) {
            int c = n0 + wn*64 + nt*8 + 2*t;
            if (HOUT) {
                __half* Ch = (__half*)Cout;
                *(unsigned int*)&Ch[(size_t)r*N + c]     = pk2(acc[mt][nt][0], acc[mt][nt][1]);
                *(unsigned int*)&Ch[(size_t)(r+8)*N + c] = pk2(acc[mt][nt][2], acc[mt][nt][3]);
            } else {
                float* Cf = (float*)Cout;
                *(float2*)&Cf[(size_t)r*N + c]     = make_float2(acc[mt][nt][0], acc[mt][nt][1]);
                *(float2*)&Cf[(size_t)(r+8)*N + c] = make_float2(acc[mt][nt][2], acc[mt][nt][3]);
            }
        }
    }
}

// ---------------- fp16 mma attention with key compaction ----------------------------
// grid (T/128, H, B), block 256 (8 warps). Two-pass flash over COMPACTED key tiles.
// exp via ex2.approx.f16x2 (one MUFU per score pair); P stored unnormalized; 1/l
// folded into O registers and importance sums.
#define KST 72
#define VST 72

__device__ __forceinline__ void stageG(__half* dst, const __half* src,
                                       const int* __restrict__ cidx, int kbase, int tid) {
    #pragma unroll
    for (int i = tid; i < 512; i += 256) {
        int r = i >> 3, c8 = (i & 7)*8;
        int orig = cidx[kbase + r];
        if (orig > TT-1) orig = TT-1;
        cp16(dst + r*KST + c8, src + (size_t)orig*C3 + c8);
    }
}

__global__ __launch_bounds__(256, 2) void attn_mma(const int* __restrict__ amask) {
    extern __shared__ __half smh[];
    __half* Ks = smh;                      // [2][64*KST]
    __half* Vs = smh + 2*64*KST;           // [2][64*VST]
    __half* Ps = Vs + 2*64*VST;            // [128*KST] (Q staging, then unnormalized P)
    int* ci    = (int*)(Ps + 128*KST);     // [2][64] compacted orig indices

    const int tid = threadIdx.x;
    const int lane = tid & 31, warp = tid >> 5;
    const int g = lane >> 2, t = lane & 3;
    const int qt = (NQT - 1) - blockIdx.x;
    const int h = blockIdx.y, b = blockIdx.z;
    const int qbase = qt*128;

    const int cnt = g_cnt[b*NQT + qt];
    const int nkt = (cnt + 63) >> 6;
    const int* cidx = g_cidx[b];

    const __half* qsrc = g_qkvh + (size_t)(b*TT+qbase)*C3 + h*HS;
    const __half* kall = g_qkvh + (size_t)(b*TT)*C3 + CC + h*HS;
    const __half* vall = g_qkvh + (size_t)(b*TT)*C3 + 2*CC + h*HS;

    const int wrow0 = qbase + warp*16;
    const int gr0 = wrow0 + g;
    const int gr1 = gr0 + 8;

    const int x4_lr = lane & 15;
    const int x4_lc = (lane >> 4) * 8;
    const int x2_lr = lane & 7;
    const int x2_lc = ((lane >> 3) & 1) * 8;

    // ---- prologue: stage Q (128 rows) -> Ps and K tile 0 ----
    #pragma unroll
    for (int i = tid; i < 1024; i += 256) {
        int r = i >> 3, c8 = (i & 7)*8;
        cp16(Ps + r*KST + c8, qsrc + (size_t)r*C3 + c8);
    }
    stageG(Ks, kall, cidx, 0, tid);
    if (tid < 64) ci[tid] = cidx[tid];
    CP_COMMIT();
    CP_WAIT0();
    __syncthreads();

    unsigned int qa[4][4];
    #pragma unroll
    for (int c = 0; c < 4; c++)
        ldsm_x4(qa[c], &Ps[(warp*16 + x4_lr)*KST + 16*c + x4_lc]);

    float l0 = 0.f, l1 = 0.f;

    // ================= Pass A: row sums (half2 exp) =================
    for (int kt = 0; kt < nkt; kt++) {
        const int kbase = kt*64;
        CP_WAIT0();
        __syncthreads();
        if (kt + 1 < nkt) {
            stageG(Ks + ((kt+1)&1)*64*KST, kall, cidx, kbase+64, tid);
            if (tid < 64) ci[((kt+1)&1)*64 + tid] = cidx[kbase+64 + tid];
        }
        CP_COMMIT();

        const __half* K0 = Ks + (kt&1)*64*KST;
        const int* cit = ci + (kt&1)*64;

        float s[8][4];
        #pragma unroll
        for (int j = 0; j < 8; j++) { s[j][0]=s[j][1]=s[j][2]=s[j][3]=0.f; }
        #pragma unroll
        for (int c = 0; c < 4; c++) {
            #pragma unroll
            for (int j = 0; j < 8; j++) {
                unsigned int bf[2];
                ldsm_x2(bf, &K0[(8*j + x2_lr)*KST + 16*c + x2_lc]);
                mma_f16(s[j], qa[c], bf);
            }
        }
        float ts0 = 0.f, ts1 = 0.f;
        if (cit[63] <= wrow0) {      // interior
            #pragma unroll
            for (int j = 0; j < 8; j++) {
                __half2 e01 = hexp2(__floats2half2_rn(s[j][0]*C1SC, s[j][1]*C1SC));
                __half2 e23 = hexp2(__floats2half2_rn(s[j][2]*C1SC, s[j][3]*C1SC));
                float2 f01 = __half22float2(e01), f23 = __half22float2(e23);
                ts0 += f01.x + f01.y;
                ts1 += f23.x + f23.y;
            }
        } else {                     // diagonal/tail
            #pragma unroll
            for (int j = 0; j < 8; j++) {
                int c0 = cit[8*j+2*t], c1 = cit[8*j+2*t+1];
                float v0 = s[j][0]*C1SC; if (c0 > gr0) v0 = NEGBIG;
                float v1 = s[j][1]*C1SC; if (c1 > gr0) v1 = NEGBIG;
                float v2 = s[j][2]*C1SC; if (c0 > gr1) v2 = NEGBIG;
                float v3 = s[j][3]*C1SC; if (c1 > gr1) v3 = NEGBIG;
                __half2 e01 = hexp2(__floats2half2_rn(v0, v1));
                __half2 e23 = hexp2(__floats2half2_rn(v2, v3));
                float2 f01 = __half22float2(e01), f23 = __half22float2(e23);
                ts0 += f01.x + f01.y;
                ts1 += f23.x + f23.y;
            }
        }
        ts0 += __shfl_xor_sync(0xffffffffu, ts0, 1);
        ts0 += __shfl_xor_sync(0xffffffffu, ts0, 2);
        ts1 += __shfl_xor_sync(0xffffffffu, ts1, 1);
        ts1 += __shfl_xor_sync(0xffffffffu, ts1, 2);
        l0 += ts0;
        l1 += ts1;
    }
    const float li0 = 1.0f/l0, li1 = 1.0f/l1;

    // ================= Pass B: output + importance =================
    float o[8][4];
    #pragma unroll
    for (int j = 0; j < 8; j++) { o[j][0]=o[j][1]=o[j][2]=o[j][3]=0.f; }

    __syncthreads();
    stageG(Ks, kall, cidx, 0, tid);
    stageG(Vs, vall, cidx, 0, tid);
    if (tid < 64) ci[tid] = cidx[tid];
    CP_COMMIT();

    for (int kt = 0; kt < nkt; kt++) {
        const int kbase = kt*64;
        CP_WAIT0();
        __syncthreads();
        if (kt + 1 < nkt) {
            stageG(Ks + ((kt+1)&1)*64*KST, kall, cidx, kbase+64, tid);
            stageG(Vs + ((kt+1)&1)*64*VST, vall, cidx, kbase+64, tid);
            if (tid < 64) ci[((kt+1)&1)*64 + tid] = cidx[kbase+64 + tid];
        }
        CP_COMMIT();

        const __half* K0 = Ks + (kt&1)*64*KST;
        const __half* V0 = Vs + (kt&1)*64*VST;
        const int* cit = ci + (kt&1)*64;

        float s[8][4];
        #pragma unroll
        for (int j = 0; j < 8; j++) { s[j][0]=s[j][1]=s[j][2]=s[j][3]=0.f; }
        #pragma unroll
        for (int c = 0; c < 4; c++) {
            #pragma unroll
            for (int j = 0; j < 8; j++) {
                unsigned int bf[2];
                ldsm_x2(bf, &K0[(8*j + x2_lr)*KST + 16*c + x2_lc]);
                mma_f16(s[j], qa[c], bf);
            }
        }
        const bool interior = (cit[63] <= wrow0);
        #pragma unroll
        for (int j = 0; j < 8; j++) {
            int c0 = cit[8*j+2*t], c1 = cit[8*j+2*t+1];
            float v0 = s[j][0]*C1SC;
            float v1 = s[j][1]*C1SC;
            float v2 = s[j][2]*C1SC;
            float v3 = s[j][3]*C1SC;
            if (!interior) {
                if (c0 > gr0) v0 = NEGBIG;
                if (c1 > gr0) v1 = NEGBIG;
                if (c0 > gr1) v2 = NEGBIG;
                if (c1 > gr1) v3 = NEGBIG;
            }
            __half2 e01 = hexp2(__floats2half2_rn(v0, v1));   // row gr0, cols c0,c1
            __half2 e23 = hexp2(__floats2half2_rn(v2, v3));   // row gr1, cols c0,c1
            *(__half2*)&Ps[(warp*16+g)*KST   + 8*j + 2*t] = e01;
            *(__half2*)&Ps[(warp*16+g+8)*KST + 8*j + 2*t] = e23;
            float2 f01 = __half22float2(e01), f23 = __half22float2(e23);
            float cA = f01.x*li0 + f23.x*li1;
            float cB = f01.y*li0 + f23.y*li1;
            cA += __shfl_xor_sync(0xffffffffu, cA, 4);
            cA += __shfl_xor_sync(0xffffffffu, cA, 8);
            cA += __shfl_xor_sync(0xffffffffu, cA, 16);
            cB += __shfl_xor_sync(0xffffffffu, cB, 4);
            cB += __shfl_xor_sync(0xffffffffu, cB, 8);
            cB += __shfl_xor_sync(0xffffffffu, cB, 16);
            if (g == 0) {
                atomicAdd(&g_imp[b*TT + c0], cA);
                atomicAdd(&g_imp[b*TT + c1], cB);
            }
        }
        // O += E @ V  (unnormalized; V row-major, B-frags via ldmatrix trans)
        #pragma unroll
        for (int c = 0; c < 4; c++) {
            unsigned int pa[4];
            ldsm_x4(pa, &Ps[(warp*16 + x4_lr)*KST + 16*c + x4_lc]);
            #pragma unroll
            for (int j = 0; j < 8; j++) {
                unsigned int bv[2];
                ldsm_x2_t(bv, &V0[(16*c + (lane & 15))*VST + 8*j]);
                mma_f16(o[j], pa, bv);
            }
        }
    }

    // write O to g_atty (half), applying 1/l per row
    __half* ydst = g_atty + (size_t)(b*TT)*CC + h*HS;
    #pragma unroll
    for (int j = 0; j < 8; j++) {
        int col = 8*j + 2*t;
        *(unsigned int*)&ydst[(size_t)gr0*CC + col] = pk2(o[j][0]*li0, o[j][1]*li0);
        *(unsigned int*)&ydst[(size_t)gr1*CC + col] = pk2(o[j][2]*li1, o[j][3]*li1);
    }
}

__global__ void zero_imp_kernel() {
    int i = blockIdx.x*256 + threadIdx.x;
    if (i < BB*TT + 1) g_imp[i] = 0.f;
}

__global__ void finalize_imp_kernel(float* __restrict__ out) {
    int i = blockIdx.x*256 + threadIdx.x;
    if (i < BB*TT) out[i] = g_imp[i] * (1.0f / (HH * (float)TT));
}

extern "C" void kernel_launch(void* const* d_in, const int* in_sizes, int n_in,
                              void* d_out, int out_size) {
    const float* x      = (const float*)d_in[0];
    const int*   amask  = (const int*)d_in[1];
    const float* w_attn = (const float*)d_in[2];
    const float* w_proj = (const float*)d_in[3];
    float* out = (float*)d_out;

    __half *qkvhp, *attyp, *xhp, *wahp, *wphp;
    cudaGetSymbolAddress((void**)&qkvhp, g_qkvh);
    cudaGetSymbolAddress((void**)&attyp, g_atty);
    cudaGetSymbolAddress((void**)&xhp, g_xh);
    cudaGetSymbolAddress((void**)&wahp, g_wah);
    cudaGetSymbolAddress((void**)&wphp, g_wph);

    const int ASMEM = (2*64*KST + 2*64*VST + 128*KST)*2 + 2*64*4;  // 55,808 B
    cudaFuncSetAttribute(attn_mma, cudaFuncAttributeMaxDynamicSharedMemorySize, ASMEM);
    const int GSMEM = 3*2*GTILEH*2;  // 110,592 B
    cudaFuncSetAttribute(gemm_f16<1>, cudaFuncAttributeMaxDynamicSharedMemorySize, GSMEM);
    cudaFuncSetAttribute(gemm_f16<0>, cudaFuncAttributeMaxDynamicSharedMemorySize, GSMEM);

    // 0) convert x; transpose weights; compact mask
    cvt_h_kernel<<<(BB*TT*CC/4 + 255)/256, 256>>>((const float4*)x, (uint2*)xhp, BB*TT*CC/4);
    transpose_h_kernel<<<dim3(CC/32, C3/32), dim3(32,8)>>>(w_attn, wahp, CC, C3);
    transpose_h_kernel<<<dim3(CC/32, CC/32), dim3(32,8)>>>(w_proj, wphp, CC, CC);
    compact_kernel<<<BB, 256>>>(amask);
    // 1) qkv = x @ w_attn
    gemm_f16<1><<<dim3(C3/128, (BB*TT)/128), 128, GSMEM>>>(xhp, wahp, qkvhp, BB*TT, C3, CC);
    // 2) zero importance accumulator
    zero_imp_kernel<<<(BB*TT + 256)/256, 256>>>();
    // 3) attention + importance over compacted keys
    attn_mma<<<dim3(NQT, HH, BB), 256, ASMEM>>>(amask);
    // 4) importance -> d_out tail
    finalize_imp_kernel<<<(BB*TT + 255)/256, 256>>>(out + (size_t)BB*TT*CC);
    // 5) y = atty @ w_proj -> d_out head (fp32 out)
    gemm_f16<0><<<dim3(CC/128, (BB*TT)/128), 128, GSMEM>>>(attyp, wphp, out, BB*TT, CC, CC);
}